// round 2
// baseline (speedup 1.0000x reference)
#include <cuda_runtime.h>
#include <cuda_bf16.h>

#define NTOK 8192
#define DIN  256
#define DOUT 256
#define NE   16
#define NH   512

// Scratch (device globals; no runtime allocation allowed)
__device__ float g_Hg[NTOK * NH];      // gating hidden activations
__device__ int   g_cnt[NE];            // per-expert token counts
__device__ int   g_rtok[NE * NTOK];    // per-expert token lists
__device__ float g_rgate[NE * NTOK];   // per-expert gate values

// ---------------------------------------------------------------------------
// 32-row GEMM, 512 threads, 1 col/thread, software-pipelined weight loads.
// S: smem [32][KDIM]. W: global (col c, row i at W + i*ws + c).
// ---------------------------------------------------------------------------
template<int KDIM>
__device__ __forceinline__ void gemm_32rows(
    const float* __restrict__ S,
    const float* __restrict__ W, long ws,
    const float* __restrict__ bias,
    float* __restrict__ O, long ostride, bool do_relu, int c)
{
    float acc[32];
#pragma unroll
    for (int r = 0; r < 32; ++r) acc[r] = 0.f;

    const float* wp = W + c;
    float w0 = wp[0];
    float w1 = wp[ws];
    float w2 = wp[2 * ws];
    float w3 = wp[3 * ws];

#pragma unroll 1
    for (int i = 0; i < KDIM - 4; i += 4) {
        // prefetch next chunk (hides L2 latency behind the 128 FFMAs below)
        const float* wn = W + (long)(i + 4) * ws + c;
        float n0 = wn[0];
        float n1 = wn[ws];
        float n2 = wn[2 * ws];
        float n3 = wn[3 * ws];
#pragma unroll
        for (int r = 0; r < 32; ++r) {
            float4 xv = *(const float4*)(S + r * KDIM + i);  // broadcast LDS.128
            acc[r] = fmaf(xv.x, w0, acc[r]);
            acc[r] = fmaf(xv.y, w1, acc[r]);
            acc[r] = fmaf(xv.z, w2, acc[r]);
            acc[r] = fmaf(xv.w, w3, acc[r]);
        }
        w0 = n0; w1 = n1; w2 = n2; w3 = n3;
    }
    {   // last chunk
        const int i = KDIM - 4;
#pragma unroll
        for (int r = 0; r < 32; ++r) {
            float4 xv = *(const float4*)(S + r * KDIM + i);
            acc[r] = fmaf(xv.x, w0, acc[r]);
            acc[r] = fmaf(xv.y, w1, acc[r]);
            acc[r] = fmaf(xv.z, w2, acc[r]);
            acc[r] = fmaf(xv.w, w3, acc[r]);
        }
    }
    float bb = bias[c];
#pragma unroll
    for (int r = 0; r < 32; ++r) {
        float v = acc[r] + bb;
        if (do_relu) v = fmaxf(v, 0.f);
        O[(long)r * ostride + c] = v;
    }
}

// ---------------------------------------------------------------------------
__global__ void zero_cnt_kernel() {
    if (threadIdx.x < NE) g_cnt[threadIdx.x] = 0;
}

// ---------------------------------------------------------------------------
// K1: gating hidden = relu(x @ gate_w + gate_b)  -> g_Hg [8192, 512]
// ---------------------------------------------------------------------------
__global__ __launch_bounds__(512) void gate_h_kernel(
    const float* __restrict__ x,
    const float* __restrict__ gw,
    const float* __restrict__ gb)
{
    __shared__ float Xs[32 * DIN];
    const int tid = threadIdx.x;
    const int t0 = blockIdx.x * 32;
    for (int idx = tid; idx < 32 * DIN; idx += 512)
        Xs[idx] = x[(long)t0 * DIN + idx];
    __syncthreads();
    gemm_32rows<DIN>(Xs, gw, NH, gb, g_Hg + (long)t0 * NH, NH, true, tid);
}

// ---------------------------------------------------------------------------
// K2: logits = Hg @ gate_out_w + gate_out_b; top-2; softmax; routing append
// ---------------------------------------------------------------------------
__global__ __launch_bounds__(128) void gate_route_kernel(
    const float* __restrict__ gow,
    const float* __restrict__ gob)
{
    extern __shared__ float sm2[];
    float* Gw = sm2;               // [512*16]
    float* Gb = Gw + NH * NE;      // [16]
    float* Ht = Gb + 16;           // [128][65] padded

    const int tid = threadIdx.x;
    for (int idx = tid; idx < NH * NE; idx += 128) Gw[idx] = gow[idx];
    if (tid < NE) Gb[tid] = gob[tid];

    const int tok0 = blockIdx.x * 128;
    float acc[NE];
#pragma unroll
    for (int e = 0; e < NE; ++e) acc[e] = 0.f;

    for (int hb = 0; hb < NH; hb += 64) {
        __syncthreads();
        for (int idx = tid; idx < 128 * 64; idx += 128) {
            int r = idx >> 6, h = idx & 63;
            Ht[r * 65 + h] = g_Hg[(long)(tok0 + r) * NH + hb + h];
        }
        __syncthreads();
#pragma unroll 8
        for (int hl = 0; hl < 64; ++hl) {
            float v = Ht[tid * 65 + hl];
            const float4* gp = (const float4*)(Gw + (hb + hl) * NE);
            float4 g0v = gp[0], g1v = gp[1], g2v = gp[2], g3v = gp[3];
            acc[0]  = fmaf(v, g0v.x, acc[0]);
            acc[1]  = fmaf(v, g0v.y, acc[1]);
            acc[2]  = fmaf(v, g0v.z, acc[2]);
            acc[3]  = fmaf(v, g0v.w, acc[3]);
            acc[4]  = fmaf(v, g1v.x, acc[4]);
            acc[5]  = fmaf(v, g1v.y, acc[5]);
            acc[6]  = fmaf(v, g1v.z, acc[6]);
            acc[7]  = fmaf(v, g1v.w, acc[7]);
            acc[8]  = fmaf(v, g2v.x, acc[8]);
            acc[9]  = fmaf(v, g2v.y, acc[9]);
            acc[10] = fmaf(v, g2v.z, acc[10]);
            acc[11] = fmaf(v, g2v.w, acc[11]);
            acc[12] = fmaf(v, g3v.x, acc[12]);
            acc[13] = fmaf(v, g3v.y, acc[13]);
            acc[14] = fmaf(v, g3v.z, acc[14]);
            acc[15] = fmaf(v, g3v.w, acc[15]);
        }
    }

    // top-2 (strict > matches jax.lax.top_k first-index tie behavior)
    float v0 = -1e30f, v1 = -1e30f;
    int i0 = 0, i1 = 0;
#pragma unroll
    for (int e = 0; e < NE; ++e) {
        float l = acc[e] + Gb[e];
        if (l > v0)      { v1 = v0; i1 = i0; v0 = l; i0 = e; }
        else if (l > v1) { v1 = l;  i1 = e; }
    }
    float e1 = __expf(v1 - v0);
    float s  = 1.f + e1;
    float ga = 1.f / s;
    float gb2 = e1 / s;

    const int tok = tok0 + tid;
    int p0 = atomicAdd(&g_cnt[i0], 1);
    g_rtok[i0 * NTOK + p0]  = tok;
    g_rgate[i0 * NTOK + p0] = ga;
    int p1 = atomicAdd(&g_cnt[i1], 1);
    g_rtok[i1 * NTOK + p1]  = tok;
    g_rgate[i1 * NTOK + p1] = gb2;
}

// ---------------------------------------------------------------------------
// K3: per-expert fused 3-layer MLP over 32-token tiles + gated scatter-add
// grid = (32 tile-slots, 16 experts), tile-stride loop per block.
// 512 threads, 160 KB smem, 1 CTA/SM.
// ---------------------------------------------------------------------------
__global__ __launch_bounds__(512) void expert_kernel(
    const float* __restrict__ x,
    const float* __restrict__ w1, const float* __restrict__ b1,
    const float* __restrict__ w2, const float* __restrict__ b2,
    const float* __restrict__ w3, const float* __restrict__ b3,
    float* __restrict__ out)
{
    const int e = blockIdx.y;
    const int cnt = g_cnt[e];

    extern __shared__ float sm[];
    float* Xs = sm;                 // [32][256]  32 KB
    float* H1 = Xs + 32 * DIN;      // [32][512]  64 KB
    float* H2 = H1 + 32 * NH;       // [32][512]  64 KB
    __shared__ int   toks[32];
    __shared__ float gts[32];

    const int tid = threadIdx.x;

    for (int base = blockIdx.x * 32; base < cnt; base += 32 * 32) {
        const int m = min(32, cnt - base);

        if (tid < 32) {
            if (tid < m) {
                toks[tid] = g_rtok[e * NTOK + base + tid];
                gts[tid]  = g_rgate[e * NTOK + base + tid];
            } else {
                toks[tid] = 0; gts[tid] = 0.f;
            }
        }
        __syncthreads();

        for (int idx = tid; idx < 32 * DIN; idx += 512) {
            int r = idx >> 8, i = idx & 255;
            Xs[idx] = (r < m) ? x[(long)toks[r] * DIN + i] : 0.f;
        }
        __syncthreads();

        // h1 = relu(x @ W1[e] + b1[e])   W1: [DIN, E, H], row stride E*H
        gemm_32rows<DIN>(Xs, w1 + e * NH, (long)NE * NH, b1 + e * NH, H1, NH, true, tid);
        __syncthreads();

        // h2 = relu(h1 @ W2[e] + b2[e])  W2: [H, E, H]
        gemm_32rows<NH>(H1, w2 + e * NH, (long)NE * NH, b2 + e * NH, H2, NH, true, tid);
        __syncthreads();

        // y = h2 @ W3[e] + b3[e]; out[tok] += gate * y   W3: [H, E, DOUT]
        // 512 threads / 256 cols: rows split 16/16, full K per thread ->
        // exactly one atomicAdd per (row, col) per expert (deterministic).
        {
            const int c  = tid & 255;
            const int r0 = (tid >> 8) * 16;
            float acc[16];
#pragma unroll
            for (int r = 0; r < 16; ++r) acc[r] = 0.f;

            const long ws = (long)NE * DOUT;
            const float* Wb = w3 + e * DOUT + c;
            float w0v = Wb[0];
            float w1v = Wb[ws];
            float w2v = Wb[2 * ws];
            float w3v = Wb[3 * ws];

#pragma unroll 1
            for (int i = 0; i < NH - 4; i += 4) {
                const float* wn = Wb + (long)(i + 4) * ws;
                float n0 = wn[0];
                float n1 = wn[ws];
                float n2 = wn[2 * ws];
                float n3 = wn[3 * ws];
#pragma unroll
                for (int r = 0; r < 16; ++r) {
                    float4 xv = *(const float4*)(H2 + (r0 + r) * NH + i);
                    acc[r] = fmaf(xv.x, w0v, acc[r]);
                    acc[r] = fmaf(xv.y, w1v, acc[r]);
                    acc[r] = fmaf(xv.z, w2v, acc[r]);
                    acc[r] = fmaf(xv.w, w3v, acc[r]);
                }
                w0v = n0; w1v = n1; w2v = n2; w3v = n3;
            }
            {
                const int i = NH - 4;
#pragma unroll
                for (int r = 0; r < 16; ++r) {
                    float4 xv = *(const float4*)(H2 + (r0 + r) * NH + i);
                    acc[r] = fmaf(xv.x, w0v, acc[r]);
                    acc[r] = fmaf(xv.y, w1v, acc[r]);
                    acc[r] = fmaf(xv.z, w2v, acc[r]);
                    acc[r] = fmaf(xv.w, w3v, acc[r]);
                }
            }
            float bb = b3[e * DOUT + c];
#pragma unroll
            for (int r = 0; r < 16; ++r) {
                int row = r0 + r;
                if (row < m)
                    atomicAdd(&out[(long)toks[row] * DOUT + c], gts[row] * (acc[r] + bb));
            }
        }
        __syncthreads();   // protect toks/Xs/H2 before next tile
    }
}

// ---------------------------------------------------------------------------
extern "C" void kernel_launch(void* const* d_in, const int* in_sizes, int n_in,
                              void* d_out, int out_size)
{
    const float* x   = (const float*)d_in[0];
    const float* gw  = (const float*)d_in[1];
    const float* gb  = (const float*)d_in[2];
    const float* gow = (const float*)d_in[3];
    const float* gob = (const float*)d_in[4];
    const float* w1  = (const float*)d_in[5];
    const float* b1  = (const float*)d_in[6];
    const float* w2  = (const float*)d_in[7];
    const float* b2  = (const float*)d_in[8];
    const float* w3  = (const float*)d_in[9];
    const float* b3  = (const float*)d_in[10];
    float* out = (float*)d_out;

    const size_t sm2 = (size_t)(NH * NE + 16 + 128 * 65) * sizeof(float);   // ~66 KB
    const size_t sm3 = (size_t)(32 * DIN + 2 * 32 * NH) * sizeof(float);    // 160 KB
    cudaFuncSetAttribute(gate_route_kernel,
                         cudaFuncAttributeMaxDynamicSharedMemorySize, (int)sm2);
    cudaFuncSetAttribute(expert_kernel,
                         cudaFuncAttributeMaxDynamicSharedMemorySize, (int)sm3);

    cudaMemsetAsync(out, 0, (size_t)NTOK * DOUT * sizeof(float));
    zero_cnt_kernel<<<1, 32>>>();
    gate_h_kernel<<<NTOK / 32, 512>>>(x, gw, gb);
    gate_route_kernel<<<NTOK / 128, 128, sm2>>>(gow, gob);
    expert_kernel<<<dim3(32, NE), 512, sm3>>>(x, w1, b1, w2, b2, w3, b3, out);
}

// round 3
// speedup vs baseline: 1.5160x; 1.5160x over previous
#include <cuda_runtime.h>
#include <cuda_bf16.h>

#define NTOK 8192
#define DIN  256
#define DOUT 256
#define NE   16
#define NH   512

// Scratch (device globals; no runtime allocation allowed)
__device__ float g_Hg[NTOK * NH];      // gating hidden activations
__device__ int   g_cnt[NE];            // per-expert token counts
__device__ int   g_rtok[NE * NTOK];    // per-expert token lists
__device__ float g_rgate[NE * NTOK];   // per-expert gate values

// Packed fp32x2 helpers (FFMA2: only reachable via PTX fma.rn.f32x2)
#define FMA2(d, a, b) asm("fma.rn.f32x2 %0, %1, %2, %0;" : "+l"(d) : "l"(a), "l"(b))
#define DUP2(d, s)    asm("mov.b64 %0, {%1, %1};" : "=l"(d) : "f"(s))
#define UNPK(lo, hi, s) asm("mov.b64 {%0, %1}, %2;" : "=f"(lo), "=f"(hi) : "l"(s))

// ---------------------------------------------------------------------------
// Transposed tile loader: St[k][r] (k = feature, r = row/token), 256 threads.
// Coalesced gmem reads; lane-rotated smem stores (conflict-free).
// ---------------------------------------------------------------------------
__device__ __forceinline__ void load_tileT(
    float* __restrict__ St, const float* __restrict__ x,
    const int* __restrict__ toks, int m, int tid)
{
    const int wid = tid >> 5, lane = tid & 31;
    const int fb = wid * 32;                 // 8 warps x 32 features = DIN
    float v[32];
#pragma unroll
    for (int r = 0; r < 32; ++r)
        v[r] = (r < m) ? x[(long)toks[r] * DIN + fb + lane] : 0.f;
#pragma unroll
    for (int rr = 0; rr < 32; ++rr) {
        int r = (rr + lane) & 31;
        St[(fb + lane) * 32 + r] = v[r];
    }
}

// ---------------------------------------------------------------------------
// Packed GEMM mainloop: 32 rows (16 packed pairs) x 2 cols per thread.
// St: smem [KDIM][32]. W col c, row k at W + k*ws + c.
// acc pre-initialized with packed bias.
// ---------------------------------------------------------------------------
template<int KDIM>
__device__ __forceinline__ void gemm_coreT(
    const float* __restrict__ St,
    const float* __restrict__ W, long ws,
    int c0, int c1,
    unsigned long long* __restrict__ accA,
    unsigned long long* __restrict__ accB)
{
#pragma unroll 2
    for (int k = 0; k < KDIM; k += 4) {
        const float* wp = W + (long)k * ws;
        unsigned long long ua[4], ub[4];
#pragma unroll
        for (int j = 0; j < 4; ++j) {
            float wa = wp[(long)j * ws + c0];
            float wb = wp[(long)j * ws + c1];
            DUP2(ua[j], wa);
            DUP2(ub[j], wb);
        }
#pragma unroll
        for (int j = 0; j < 4; ++j) {
            const ulonglong2* xp = (const ulonglong2*)(St + (k + j) * 32);
#pragma unroll
            for (int p = 0; p < 8; ++p) {
                ulonglong2 X = xp[p];        // rows 4p..4p+3 (2 packed pairs)
                FMA2(accA[2 * p],     X.x, ua[j]);
                FMA2(accA[2 * p + 1], X.y, ua[j]);
                FMA2(accB[2 * p],     X.x, ub[j]);
                FMA2(accB[2 * p + 1], X.y, ub[j]);
            }
        }
    }
}

// ---------------------------------------------------------------------------
__global__ void zero_cnt_kernel() {
    if (threadIdx.x < NE) g_cnt[threadIdx.x] = 0;
}

// ---------------------------------------------------------------------------
// K1: gating hidden = relu(x @ gate_w + gate_b) -> g_Hg [8192, 512] (normal)
// ---------------------------------------------------------------------------
__global__ __launch_bounds__(256) void gate_h_kernel(
    const float* __restrict__ x,
    const float* __restrict__ gw,
    const float* __restrict__ gb)
{
    __shared__ __align__(16) float Xs[DIN * 32];   // transposed [256][32]
    __shared__ int toks[32];
    const int tid = threadIdx.x;
    const int t0 = blockIdx.x * 32;
    if (tid < 32) toks[tid] = t0 + tid;
    __syncthreads();
    load_tileT(Xs, x, toks, 32, tid);
    __syncthreads();

    const int c0 = tid, c1 = tid + 256;
    unsigned long long accA[16], accB[16];
    float bb0 = gb[c0], bb1 = gb[c1];
#pragma unroll
    for (int p = 0; p < 16; ++p) { DUP2(accA[p], bb0); DUP2(accB[p], bb1); }

    gemm_coreT<DIN>(Xs, gw, NH, c0, c1, accA, accB);

#pragma unroll
    for (int p = 0; p < 16; ++p) {
        float lo, hi;
        UNPK(lo, hi, accA[p]);
        g_Hg[(long)(t0 + 2 * p) * NH + c0]     = fmaxf(lo, 0.f);
        g_Hg[(long)(t0 + 2 * p + 1) * NH + c0] = fmaxf(hi, 0.f);
        UNPK(lo, hi, accB[p]);
        g_Hg[(long)(t0 + 2 * p) * NH + c1]     = fmaxf(lo, 0.f);
        g_Hg[(long)(t0 + 2 * p + 1) * NH + c1] = fmaxf(hi, 0.f);
    }
}

// ---------------------------------------------------------------------------
// K2: logits = Hg @ gate_out_w + gate_out_b; top-2; softmax; routing append
// ---------------------------------------------------------------------------
__global__ __launch_bounds__(128) void gate_route_kernel(
    const float* __restrict__ gow,
    const float* __restrict__ gob)
{
    extern __shared__ float sm2[];
    float* Gw = sm2;               // [512*16]
    float* Gb = Gw + NH * NE;      // [16]
    float* Ht = Gb + 16;           // [128][65] padded

    const int tid = threadIdx.x;
    for (int idx = tid; idx < NH * NE; idx += 128) Gw[idx] = gow[idx];
    if (tid < NE) Gb[tid] = gob[tid];

    const int tok0 = blockIdx.x * 128;
    float acc[NE];
#pragma unroll
    for (int e = 0; e < NE; ++e) acc[e] = 0.f;

    for (int hb = 0; hb < NH; hb += 64) {
        __syncthreads();
        for (int idx = tid; idx < 128 * 64; idx += 128) {
            int r = idx >> 6, h = idx & 63;
            Ht[r * 65 + h] = g_Hg[(long)(tok0 + r) * NH + hb + h];
        }
        __syncthreads();
#pragma unroll 8
        for (int hl = 0; hl < 64; ++hl) {
            float v = Ht[tid * 65 + hl];
            const float4* gp = (const float4*)(Gw + (hb + hl) * NE);
            float4 g0v = gp[0], g1v = gp[1], g2v = gp[2], g3v = gp[3];
            acc[0]  = fmaf(v, g0v.x, acc[0]);
            acc[1]  = fmaf(v, g0v.y, acc[1]);
            acc[2]  = fmaf(v, g0v.z, acc[2]);
            acc[3]  = fmaf(v, g0v.w, acc[3]);
            acc[4]  = fmaf(v, g1v.x, acc[4]);
            acc[5]  = fmaf(v, g1v.y, acc[5]);
            acc[6]  = fmaf(v, g1v.z, acc[6]);
            acc[7]  = fmaf(v, g1v.w, acc[7]);
            acc[8]  = fmaf(v, g2v.x, acc[8]);
            acc[9]  = fmaf(v, g2v.y, acc[9]);
            acc[10] = fmaf(v, g2v.z, acc[10]);
            acc[11] = fmaf(v, g2v.w, acc[11]);
            acc[12] = fmaf(v, g3v.x, acc[12]);
            acc[13] = fmaf(v, g3v.y, acc[13]);
            acc[14] = fmaf(v, g3v.z, acc[14]);
            acc[15] = fmaf(v, g3v.w, acc[15]);
        }
    }

    // top-2 (strict > matches jax.lax.top_k first-index tie behavior)
    float v0 = -1e30f, v1 = -1e30f;
    int i0 = 0, i1 = 0;
#pragma unroll
    for (int e = 0; e < NE; ++e) {
        float l = acc[e] + Gb[e];
        if (l > v0)      { v1 = v0; i1 = i0; v0 = l; i0 = e; }
        else if (l > v1) { v1 = l;  i1 = e; }
    }
    float e1 = __expf(v1 - v0);
    float s  = 1.f + e1;
    float ga = 1.f / s;
    float gb2 = e1 / s;

    const int tok = tok0 + tid;
    int p0 = atomicAdd(&g_cnt[i0], 1);
    g_rtok[i0 * NTOK + p0]  = tok;
    g_rgate[i0 * NTOK + p0] = ga;
    int p1 = atomicAdd(&g_cnt[i1], 1);
    g_rtok[i1 * NTOK + p1]  = tok;
    g_rgate[i1 * NTOK + p1] = gb2;
}

// ---------------------------------------------------------------------------
// K3: per-expert fused 3-layer MLP over 32-token tiles + gated scatter-add
// grid = (256 tiles, 16 experts); blocks past the expert's count exit early.
// All smem tiles TRANSPOSED [k][32]; lane-rotated stores avoid conflicts.
// ---------------------------------------------------------------------------
__global__ __launch_bounds__(256) void expert_kernel(
    const float* __restrict__ x,
    const float* __restrict__ w1, const float* __restrict__ b1,
    const float* __restrict__ w2, const float* __restrict__ b2,
    const float* __restrict__ w3, const float* __restrict__ b3,
    float* __restrict__ out)
{
    const int e = blockIdx.y;
    const int cnt = g_cnt[e];
    const int base = blockIdx.x * 32;
    if (base >= cnt) return;
    const int m = min(32, cnt - base);

    extern __shared__ __align__(16) float sm[];
    float* Xs = sm;                 // [256][32]  32 KB  (transposed)
    float* H1 = Xs + DIN * 32;      // [512][32]  64 KB
    float* H2 = H1 + NH * 32;       // [512][32]  64 KB
    __shared__ int   toks[32];
    __shared__ float gts[32];

    const int tid = threadIdx.x;
    const int lane = tid & 31;
    if (tid < 32) {
        if (tid < m) {
            toks[tid] = g_rtok[e * NTOK + base + tid];
            gts[tid]  = g_rgate[e * NTOK + base + tid];
        } else {
            toks[tid] = 0; gts[tid] = 0.f;
        }
    }
    __syncthreads();

    load_tileT(Xs, x, toks, m, tid);
    __syncthreads();

    const int c0 = tid, c1 = tid + 256;

    // ---- GEMM1: H1 = relu(X @ W1[e] + b1[e]);  W1 row stride NE*NH ----
    {
        unsigned long long accA[16], accB[16];
        float bb0 = b1[e * NH + c0], bb1 = b1[e * NH + c1];
#pragma unroll
        for (int p = 0; p < 16; ++p) { DUP2(accA[p], bb0); DUP2(accB[p], bb1); }

        gemm_coreT<DIN>(Xs, w1 + e * NH, (long)NE * NH, c0, c1, accA, accB);

#pragma unroll
        for (int pp = 0; pp < 16; ++pp) {          // lane-rotated, conflict-light
            int p = (pp + lane) & 15;
            float lo, hi;
            UNPK(lo, hi, accA[p]);
            *(float2*)(H1 + c0 * 32 + 2 * p) = make_float2(fmaxf(lo, 0.f), fmaxf(hi, 0.f));
            UNPK(lo, hi, accB[p]);
            *(float2*)(H1 + c1 * 32 + 2 * p) = make_float2(fmaxf(lo, 0.f), fmaxf(hi, 0.f));
        }
    }
    __syncthreads();

    // ---- GEMM2: H2 = relu(H1 @ W2[e] + b2[e]) ----
    {
        unsigned long long accA[16], accB[16];
        float bb0 = b2[e * NH + c0], bb1 = b2[e * NH + c1];
#pragma unroll
        for (int p = 0; p < 16; ++p) { DUP2(accA[p], bb0); DUP2(accB[p], bb1); }

        gemm_coreT<NH>(H1, w2 + e * NH, (long)NE * NH, c0, c1, accA, accB);

#pragma unroll
        for (int pp = 0; pp < 16; ++pp) {
            int p = (pp + lane) & 15;
            float lo, hi;
            UNPK(lo, hi, accA[p]);
            *(float2*)(H2 + c0 * 32 + 2 * p) = make_float2(fmaxf(lo, 0.f), fmaxf(hi, 0.f));
            UNPK(lo, hi, accB[p]);
            *(float2*)(H2 + c1 * 32 + 2 * p) = make_float2(fmaxf(lo, 0.f), fmaxf(hi, 0.f));
        }
    }
    __syncthreads();

    // ---- GEMM3: y = H2 @ W3[e] + b3[e]; out[tok] += gate * y ----
    // 256 threads = 256 cols; 16 packed row-pairs per thread.
    {
        const int c = tid;
        const long ws3 = (long)NE * DOUT;
        const float* W3 = w3 + e * DOUT;
        unsigned long long accO[16];
        float bb = b3[e * DOUT + c];
#pragma unroll
        for (int p = 0; p < 16; ++p) DUP2(accO[p], bb);

#pragma unroll 2
        for (int k = 0; k < NH; k += 4) {
            const float* wp = W3 + (long)k * ws3;
            unsigned long long uw[4];
#pragma unroll
            for (int j = 0; j < 4; ++j) {
                float w = wp[(long)j * ws3 + c];
                DUP2(uw[j], w);
            }
#pragma unroll
            for (int j = 0; j < 4; ++j) {
                const ulonglong2* xp = (const ulonglong2*)(H2 + (k + j) * 32);
#pragma unroll
                for (int p = 0; p < 8; ++p) {
                    ulonglong2 X = xp[p];
                    FMA2(accO[2 * p],     X.x, uw[j]);
                    FMA2(accO[2 * p + 1], X.y, uw[j]);
                }
            }
        }

#pragma unroll
        for (int p = 0; p < 16; ++p) {
            float lo, hi;
            UNPK(lo, hi, accO[p]);
            int r0 = 2 * p, r1 = 2 * p + 1;
            if (r0 < m) atomicAdd(&out[(long)toks[r0] * DOUT + c], gts[r0] * lo);
            if (r1 < m) atomicAdd(&out[(long)toks[r1] * DOUT + c], gts[r1] * hi);
        }
    }
}

// ---------------------------------------------------------------------------
extern "C" void kernel_launch(void* const* d_in, const int* in_sizes, int n_in,
                              void* d_out, int out_size)
{
    const float* x   = (const float*)d_in[0];
    const float* gw  = (const float*)d_in[1];
    const float* gb  = (const float*)d_in[2];
    const float* gow = (const float*)d_in[3];
    const float* gob = (const float*)d_in[4];
    const float* w1  = (const float*)d_in[5];
    const float* b1  = (const float*)d_in[6];
    const float* w2  = (const float*)d_in[7];
    const float* b2  = (const float*)d_in[8];
    const float* w3  = (const float*)d_in[9];
    const float* b3  = (const float*)d_in[10];
    float* out = (float*)d_out;

    const size_t sm2 = (size_t)(NH * NE + 16 + 128 * 65) * sizeof(float);   // ~66 KB
    const size_t sm3 = (size_t)(DIN * 32 + 2 * NH * 32) * sizeof(float);    // 160 KB
    cudaFuncSetAttribute(gate_route_kernel,
                         cudaFuncAttributeMaxDynamicSharedMemorySize, (int)sm2);
    cudaFuncSetAttribute(expert_kernel,
                         cudaFuncAttributeMaxDynamicSharedMemorySize, (int)sm3);

    cudaMemsetAsync(out, 0, (size_t)NTOK * DOUT * sizeof(float));
    zero_cnt_kernel<<<1, 32>>>();
    gate_h_kernel<<<NTOK / 32, 256>>>(x, gw, gb);
    gate_route_kernel<<<NTOK / 128, 128, sm2>>>(gow, gob);
    expert_kernel<<<dim3(NTOK / 32, NE), 256, sm3>>>(x, w1, b1, w2, b2, w3, b3, out);
}

// round 6
// speedup vs baseline: 3.7616x; 2.4812x over previous
#include <cuda_runtime.h>
#include <cuda_bf16.h>
#include <cstdint>

#define NTOK 8192
#define DIN  256
#define DOUT 256
#define NE   16
#define NH   512
#define SLOTS 18560   // >= 16384 + 16*127 padded routed slots

// ---------------------------------------------------------------------------
// Device scratch
// ---------------------------------------------------------------------------
__device__ float g_Hg[NTOK * NH];          // gating hidden (fp32)
__device__ int   g_cnt[NE];
__device__ int   g_off[NE];                // padded prefix offsets
__device__ int   g_rtok[NE * NTOK];
__device__ float g_rgate[NE * NTOK];

__device__ __nv_bfloat16 g_xhi[NTOK * DIN],  g_xlo[NTOK * DIN];
__device__ __nv_bfloat16 g_w1Thi[NE * NH * DIN],  g_w1Tlo[NE * NH * DIN];    // [e][n=512][k=256]
__device__ __nv_bfloat16 g_w2Thi[NE * NH * NH],   g_w2Tlo[NE * NH * NH];     // [e][512][512]
__device__ __nv_bfloat16 g_w3Thi[NE * DOUT * NH], g_w3Tlo[NE * DOUT * NH];   // [e][256][512]
__device__ __nv_bfloat16 g_h1hi[(size_t)SLOTS * NH], g_h1lo[(size_t)SLOTS * NH];
__device__ __nv_bfloat16 g_h2hi[(size_t)SLOTS * NH], g_h2lo[(size_t)SLOTS * NH];

// ---------------------------------------------------------------------------
// PTX helpers (compute_103-safe: cp.async + ldmatrix + mma.sync only)
// ---------------------------------------------------------------------------
__device__ __forceinline__ uint32_t smem_u32(const void* p) {
    uint32_t a;
    asm("{ .reg .u64 t; cvta.to.shared.u64 t, %1; cvt.u32.u64 %0, t; }" : "=r"(a) : "l"(p));
    return a;
}
#define CP16(dst, src) \
    asm volatile("cp.async.cg.shared.global [%0], [%1], 16;" :: "r"(dst), "l"(src) : "memory")
#define CP_COMMIT() asm volatile("cp.async.commit_group;" ::: "memory")
#define CP_WAIT(n)  asm volatile("cp.async.wait_group %0;" :: "n"(n) : "memory")

#define LDSM4(r, addr) \
    asm volatile("ldmatrix.sync.aligned.m8n8.x4.shared.b16 {%0,%1,%2,%3}, [%4];" \
        : "=r"((r)[0]), "=r"((r)[1]), "=r"((r)[2]), "=r"((r)[3]) : "r"(addr))

#define MMA16816(c, a, b) \
    asm volatile("mma.sync.aligned.m16n8k16.row.col.f32.bf16.bf16.f32 " \
        "{%0,%1,%2,%3}, {%4,%5,%6,%7}, {%8,%9}, {%0,%1,%2,%3};" \
        : "+f"((c)[0]), "+f"((c)[1]), "+f"((c)[2]), "+f"((c)[3]) \
        : "r"((a)[0]), "r"((a)[1]), "r"((a)[2]), "r"((a)[3]), "r"((b)[0]), "r"((b)[1]))

// Packed fp32x2 helpers (gate path)
#define FMA2(d, a, b) asm("fma.rn.f32x2 %0, %1, %2, %0;" : "+l"(d) : "l"(a), "l"(b))
#define DUP2(d, s)    asm("mov.b64 %0, {%1, %1};" : "=l"(d) : "f"(s))
#define UNPK(lo, hi, s) asm("mov.b64 {%0, %1}, %2;" : "=f"(lo), "=f"(hi) : "l"(s))

// ---------------------------------------------------------------------------
// Small prep kernels
// ---------------------------------------------------------------------------
__global__ void zero_cnt_kernel() {
    if (threadIdx.x < NE) g_cnt[threadIdx.x] = 0;
}
__global__ void prefix_kernel() {
    if (threadIdx.x == 0) {
        int off = 0;
        for (int e = 0; e < NE; ++e) {
            g_off[e] = off;
            off += ((g_cnt[e] + 127) >> 7) << 7;
        }
    }
}
__global__ void split_x_kernel(const float* __restrict__ x) {
    int i = blockIdx.x * blockDim.x + threadIdx.x;   // pair index
    float2 v = ((const float2*)x)[i];
    __nv_bfloat16 h0 = __float2bfloat16(v.x), h1 = __float2bfloat16(v.y);
    float r0 = v.x - __bfloat162float(h0), r1 = v.y - __bfloat162float(h1);
    __nv_bfloat16 l0 = __float2bfloat16(r0), l1 = __float2bfloat16(r1);
    ((uint32_t*)g_xhi)[i] = (uint32_t)__bfloat16_as_ushort(h0) | ((uint32_t)__bfloat16_as_ushort(h1) << 16);
    ((uint32_t*)g_xlo)[i] = (uint32_t)__bfloat16_as_ushort(l0) | ((uint32_t)__bfloat16_as_ushort(l1) << 16);
}

// Transpose + split: W[k][n] (row stride rs, per-expert col base e_off) -> planes [n][k]
template<int WID>
__global__ void transpose_split_kernel(const float* __restrict__ src,
                                       int e_off, long rs, int K, int N)
{
    __shared__ float t[32][33];
    const int e = blockIdx.z;
    const int n0 = blockIdx.x * 32, k0 = blockIdx.y * 32;
    const int tx = threadIdx.x, ty = threadIdx.y;
    const float* s = src + (long)e * e_off;
#pragma unroll
    for (int i = 0; i < 4; ++i)
        t[ty + 8 * i][tx] = s[(long)(k0 + ty + 8 * i) * rs + n0 + tx];
    __syncthreads();
    __nv_bfloat16* dh = (WID == 1) ? g_w1Thi : (WID == 2) ? g_w2Thi : g_w3Thi;
    __nv_bfloat16* dl = (WID == 1) ? g_w1Tlo : (WID == 2) ? g_w2Tlo : g_w3Tlo;
    dh += (size_t)e * N * K;  dl += (size_t)e * N * K;
#pragma unroll
    for (int i = 0; i < 4; ++i) {
        float v = t[tx][ty + 8 * i];
        __nv_bfloat16 h = __float2bfloat16(v);
        float r = v - __bfloat162float(h);
        size_t idx = (size_t)(n0 + ty + 8 * i) * K + k0 + tx;
        dh[idx] = h;
        dl[idx] = __float2bfloat16(r);
    }
}

// ---------------------------------------------------------------------------
// Gate hidden (scalar fp32, FFMA2) — kept exact so routing matches reference
// ---------------------------------------------------------------------------
__device__ __forceinline__ void load_tileT(
    float* __restrict__ St, const float* __restrict__ x,
    const int* __restrict__ toks, int m, int tid)
{
    const int wid = tid >> 5, lane = tid & 31;
    const int fb = wid * 32;
    float v[32];
#pragma unroll
    for (int r = 0; r < 32; ++r)
        v[r] = (r < m) ? x[(long)toks[r] * DIN + fb + lane] : 0.f;
#pragma unroll
    for (int rr = 0; rr < 32; ++rr) {
        int r = (rr + lane) & 31;
        St[(fb + lane) * 32 + r] = v[r];
    }
}

template<int KDIM>
__device__ __forceinline__ void gemm_coreT(
    const float* __restrict__ St, const float* __restrict__ W, long ws,
    int c0, int c1, unsigned long long* accA, unsigned long long* accB)
{
#pragma unroll 2
    for (int k = 0; k < KDIM; k += 4) {
        const float* wp = W + (long)k * ws;
        unsigned long long ua[4], ub[4];
#pragma unroll
        for (int j = 0; j < 4; ++j) {
            float wa = wp[(long)j * ws + c0];
            float wb = wp[(long)j * ws + c1];
            DUP2(ua[j], wa); DUP2(ub[j], wb);
        }
#pragma unroll
        for (int j = 0; j < 4; ++j) {
            const ulonglong2* xp = (const ulonglong2*)(St + (k + j) * 32);
#pragma unroll
            for (int p = 0; p < 8; ++p) {
                ulonglong2 X = xp[p];
                FMA2(accA[2 * p],     X.x, ua[j]);
                FMA2(accA[2 * p + 1], X.y, ua[j]);
                FMA2(accB[2 * p],     X.x, ub[j]);
                FMA2(accB[2 * p + 1], X.y, ub[j]);
            }
        }
    }
}

__global__ __launch_bounds__(256) void gate_h_kernel(
    const float* __restrict__ x, const float* __restrict__ gw, const float* __restrict__ gb)
{
    __shared__ __align__(16) float Xs[DIN * 32];
    __shared__ int toks[32];
    const int tid = threadIdx.x;
    const int t0 = blockIdx.x * 32;
    if (tid < 32) toks[tid] = t0 + tid;
    __syncthreads();
    load_tileT(Xs, x, toks, 32, tid);
    __syncthreads();

    const int c0 = tid, c1 = tid + 256;
    unsigned long long accA[16], accB[16];
    float bb0 = gb[c0], bb1 = gb[c1];
#pragma unroll
    for (int p = 0; p < 16; ++p) { DUP2(accA[p], bb0); DUP2(accB[p], bb1); }
    gemm_coreT<DIN>(Xs, gw, NH, c0, c1, accA, accB);
#pragma unroll
    for (int p = 0; p < 16; ++p) {
        float lo, hi;
        UNPK(lo, hi, accA[p]);
        g_Hg[(long)(t0 + 2 * p) * NH + c0]     = fmaxf(lo, 0.f);
        g_Hg[(long)(t0 + 2 * p + 1) * NH + c0] = fmaxf(hi, 0.f);
        UNPK(lo, hi, accB[p]);
        g_Hg[(long)(t0 + 2 * p) * NH + c1]     = fmaxf(lo, 0.f);
        g_Hg[(long)(t0 + 2 * p + 1) * NH + c1] = fmaxf(hi, 0.f);
    }
}

// ---------------------------------------------------------------------------
// Routing (unchanged, fp32-exact)
// ---------------------------------------------------------------------------
__global__ __launch_bounds__(128) void gate_route_kernel(
    const float* __restrict__ gow, const float* __restrict__ gob)
{
    extern __shared__ float sm2[];
    float* Gw = sm2;
    float* Gb = Gw + NH * NE;
    float* Ht = Gb + 16;

    const int tid = threadIdx.x;
    for (int idx = tid; idx < NH * NE; idx += 128) Gw[idx] = gow[idx];
    if (tid < NE) Gb[tid] = gob[tid];

    const int tok0 = blockIdx.x * 128;
    float acc[NE];
#pragma unroll
    for (int e = 0; e < NE; ++e) acc[e] = 0.f;

    for (int hb = 0; hb < NH; hb += 64) {
        __syncthreads();
        for (int idx = tid; idx < 128 * 64; idx += 128) {
            int r = idx >> 6, h = idx & 63;
            Ht[r * 65 + h] = g_Hg[(long)(tok0 + r) * NH + hb + h];
        }
        __syncthreads();
#pragma unroll 8
        for (int hl = 0; hl < 64; ++hl) {
            float v = Ht[tid * 65 + hl];
            const float4* gp = (const float4*)(Gw + (hb + hl) * NE);
            float4 g0v = gp[0], g1v = gp[1], g2v = gp[2], g3v = gp[3];
            acc[0]  = fmaf(v, g0v.x, acc[0]);   acc[1]  = fmaf(v, g0v.y, acc[1]);
            acc[2]  = fmaf(v, g0v.z, acc[2]);   acc[3]  = fmaf(v, g0v.w, acc[3]);
            acc[4]  = fmaf(v, g1v.x, acc[4]);   acc[5]  = fmaf(v, g1v.y, acc[5]);
            acc[6]  = fmaf(v, g1v.z, acc[6]);   acc[7]  = fmaf(v, g1v.w, acc[7]);
            acc[8]  = fmaf(v, g2v.x, acc[8]);   acc[9]  = fmaf(v, g2v.y, acc[9]);
            acc[10] = fmaf(v, g2v.z, acc[10]);  acc[11] = fmaf(v, g2v.w, acc[11]);
            acc[12] = fmaf(v, g3v.x, acc[12]);  acc[13] = fmaf(v, g3v.y, acc[13]);
            acc[14] = fmaf(v, g3v.z, acc[14]);  acc[15] = fmaf(v, g3v.w, acc[15]);
        }
    }

    float v0 = -1e30f, v1 = -1e30f;
    int i0 = 0, i1 = 0;
#pragma unroll
    for (int e = 0; e < NE; ++e) {
        float l = acc[e] + Gb[e];
        if (l > v0)      { v1 = v0; i1 = i0; v0 = l; i0 = e; }
        else if (l > v1) { v1 = l;  i1 = e; }
    }
    float e1 = __expf(v1 - v0);
    float s  = 1.f + e1;
    float ga = 1.f / s;
    float gb2 = e1 / s;

    const int tok = tok0 + tid;
    int p0 = atomicAdd(&g_cnt[i0], 1);
    g_rtok[i0 * NTOK + p0]  = tok;
    g_rgate[i0 * NTOK + p0] = ga;
    int p1 = atomicAdd(&g_cnt[i1], 1);
    g_rtok[i1 * NTOK + p1]  = tok;
    g_rgate[i1 * NTOK + p1] = gb2;
}

// ---------------------------------------------------------------------------
// HMMA split-bf16 GEMM. MODE 1: X->H1, 2: H1->H2, 3: H2->out (gated scatter)
// CTA: 128 M-slots x 128 N-cols, K chunked by 64, 2-stage cp.async pipeline.
// 8 warps = 4(M) x 2(N); warp tile 32x64; mma.sync m16n8k16 bf16.
// smem stage: Ahi | Alo | Bhi | Blo, 16KB each (swizzled [row][64] bf16).
// B stored [n][k] -> plain ldmatrix (NO trans) yields col-major B frags.
// ---------------------------------------------------------------------------
#define STG_BYTES 65536

template<int MODE, int KF, int NW>
__global__ __launch_bounds__(256, 1) void mma_kernel(
    const float* __restrict__ bias, float* __restrict__ outp)
{
    const int e    = blockIdx.y;
    const int tile = blockIdx.x;
    const int cnt  = g_cnt[e];
    if (tile * 128 >= cnt) return;
    const int nbase = blockIdx.z * 128;
    const int m = min(128, cnt - tile * 128);
    const int slotbase = g_off[e] + tile * 128;

    const __nv_bfloat16* Ahip = (MODE == 1) ? g_xhi : (MODE == 2) ? g_h1hi : g_h2hi;
    const __nv_bfloat16* Alop = (MODE == 1) ? g_xlo : (MODE == 2) ? g_h1lo : g_h2lo;
    const __nv_bfloat16* Bhi_e = ((MODE == 1) ? g_w1Thi : (MODE == 2) ? g_w2Thi : g_w3Thi)
                                 + (size_t)e * NW * KF;
    const __nv_bfloat16* Blo_e = ((MODE == 1) ? g_w1Tlo : (MODE == 2) ? g_w2Tlo : g_w3Tlo)
                                 + (size_t)e * NW * KF;
    __nv_bfloat16* Ohi = (MODE == 1) ? g_h1hi : g_h2hi;
    __nv_bfloat16* Olo = (MODE == 1) ? g_h1lo : g_h2lo;

    extern __shared__ char smp[];
    const uint32_t smb = smem_u32(smp);
    __shared__ int   toks[128];
    __shared__ float gts[128];
    __shared__ float sbias[128];

    const int tid  = threadIdx.x;
    const int wid  = tid >> 5, lane = tid & 31;
    const int wm   = wid & 3,  wn   = wid >> 2;

    if (tid < 128) {
        if (MODE != 2) {
            int i = tile * 128 + tid;
            bool v = (i < cnt);
            toks[tid] = v ? g_rtok[e * NTOK + i] : 0;
            gts[tid]  = v ? g_rgate[e * NTOK + i] : 0.f;
        }
        sbias[tid] = bias[e * NW + nbase + tid];
    }
    __syncthreads();

    const int NCH = KF / 64;

    // ---- async chunk loader: 16 cp.async of 16B per thread ----
    auto load_chunk = [&](int ch, int s) {
        const int kbase = ch * 64;
        const uint32_t sb = smb + s * STG_BYTES;
#pragma unroll
        for (int i = 0; i < 4; ++i) {
            int idx = tid + i * 256;          // 0..1023
            int row = idx >> 3, u = idx & 7;
            uint32_t d = sb + row * 128 + ((u ^ (row & 7)) << 4);
            long arow = (MODE == 1) ? (long)toks[row] : (long)(slotbase + row);
            const __nv_bfloat16* sa = Ahip + arow * KF + kbase + u * 8;
            CP16(d, sa);
            CP16(d + 16384, Alop + arow * KF + kbase + u * 8);
            const __nv_bfloat16* sbp = Bhi_e + (size_t)(nbase + row) * KF + kbase + u * 8;
            CP16(d + 32768, sbp);
            CP16(d + 49152, Blo_e + (size_t)(nbase + row) * KF + kbase + u * 8);
        }
        CP_COMMIT();
    };

    float acc[2][8][4];
#pragma unroll
    for (int mf = 0; mf < 2; ++mf)
#pragma unroll
        for (int nf = 0; nf < 8; ++nf)
#pragma unroll
            for (int j = 0; j < 4; ++j) acc[mf][nf][j] = 0.f;

    load_chunk(0, 0);

    for (int ch = 0; ch < NCH; ++ch) {
        if (ch + 1 < NCH) { load_chunk(ch + 1, (ch + 1) & 1); CP_WAIT(1); }
        else              { CP_WAIT(0); }
        __syncthreads();

        const uint32_t sb  = smb + (ch & 1) * STG_BYTES;
        const uint32_t aHI = sb, aLO = sb + 16384, bHI = sb + 32768, bLO = sb + 49152;

#pragma unroll
        for (int ks = 0; ks < 4; ++ks) {
            const int k0 = ks * 16;
            // A fragments (row-major 16x16 via ldmatrix.x4)
            uint32_t ahi[2][4], alo[2][4];
            {
                int r_ = (lane & 7) + ((lane >> 3) & 1) * 8;
                int ak = k0 + (lane >> 4) * 8;
#pragma unroll
                for (int mf = 0; mf < 2; ++mf) {
                    int r = wm * 32 + mf * 16 + r_;
                    uint32_t off = (uint32_t)(r * 128 + ((((ak >> 3) ^ (r & 7))) << 4));
                    LDSM4(ahi[mf], aHI + off);
                    LDSM4(alo[mf], aLO + off);
                }
            }
            // B fragments: [n][k] storage, plain ldmatrix on n-rows -> col-major frags
            uint32_t bhi[8][2], blo[8][2];
            {
                int n_ = (lane & 7) + (lane >> 4) * 8;
                int bk = k0 + ((lane >> 3) & 1) * 8;
#pragma unroll
                for (int nb = 0; nb < 4; ++nb) {
                    int n = wn * 64 + nb * 16 + n_;
                    uint32_t off = (uint32_t)(n * 128 + ((((bk >> 3) ^ (n & 7))) << 4));
                    uint32_t r4[4];
                    LDSM4(r4, bHI + off);
                    bhi[2 * nb][0] = r4[0]; bhi[2 * nb][1] = r4[1];
                    bhi[2 * nb + 1][0] = r4[2]; bhi[2 * nb + 1][1] = r4[3];
                    LDSM4(r4, bLO + off);
                    blo[2 * nb][0] = r4[0]; blo[2 * nb][1] = r4[1];
                    blo[2 * nb + 1][0] = r4[2]; blo[2 * nb + 1][1] = r4[3];
                }
            }
            // 3 split-products, interleaved so same-acc chains are 16 apart
#pragma unroll
            for (int mf = 0; mf < 2; ++mf)
#pragma unroll
                for (int nf = 0; nf < 8; ++nf) MMA16816(acc[mf][nf], ahi[mf], bhi[nf]);
#pragma unroll
            for (int mf = 0; mf < 2; ++mf)
#pragma unroll
                for (int nf = 0; nf < 8; ++nf) MMA16816(acc[mf][nf], alo[mf], bhi[nf]);
#pragma unroll
            for (int mf = 0; mf < 2; ++mf)
#pragma unroll
                for (int nf = 0; nf < 8; ++nf) MMA16816(acc[mf][nf], ahi[mf], blo[nf]);
        }
        __syncthreads();   // all warps done reading before stage is overwritten
    }

    // ---- epilogue ----
    const int grp = lane >> 2, t2 = (lane & 3) * 2;
#pragma unroll
    for (int mf = 0; mf < 2; ++mf) {
#pragma unroll
        for (int nf = 0; nf < 8; ++nf) {
            const float* c = acc[mf][nf];
            const int col = wn * 64 + nf * 8 + t2;        // 0..127 in-tile
#pragma unroll
            for (int half = 0; half < 2; ++half) {
                const int r = wm * 32 + mf * 16 + grp + half * 8;
                float v0 = c[half * 2 + 0] + sbias[col];
                float v1 = c[half * 2 + 1] + sbias[col + 1];
                if (MODE == 3) {
                    if (r < m) {
                        float g = gts[r];
                        float* orow = outp + (size_t)toks[r] * DOUT + nbase + col;
                        atomicAdd(orow,     g * v0);
                        atomicAdd(orow + 1, g * v1);
                    }
                } else {
                    v0 = fmaxf(v0, 0.f);
                    v1 = fmaxf(v1, 0.f);
                    __nv_bfloat16 h0 = __float2bfloat16(v0), h1 = __float2bfloat16(v1);
                    float r0 = v0 - __bfloat162float(h0), r1 = v1 - __bfloat162float(h1);
                    __nv_bfloat16 l0 = __float2bfloat16(r0), l1 = __float2bfloat16(r1);
                    size_t oi = (size_t)(slotbase + r) * NH + nbase + col;
                    *(uint32_t*)(Ohi + oi) =
                        (uint32_t)__bfloat16_as_ushort(h0) | ((uint32_t)__bfloat16_as_ushort(h1) << 16);
                    *(uint32_t*)(Olo + oi) =
                        (uint32_t)__bfloat16_as_ushort(l0) | ((uint32_t)__bfloat16_as_ushort(l1) << 16);
                }
            }
        }
    }
}

// ---------------------------------------------------------------------------
extern "C" void kernel_launch(void* const* d_in, const int* in_sizes, int n_in,
                              void* d_out, int out_size)
{
    const float* x   = (const float*)d_in[0];
    const float* gw  = (const float*)d_in[1];
    const float* gb  = (const float*)d_in[2];
    const float* gow = (const float*)d_in[3];
    const float* gob = (const float*)d_in[4];
    const float* w1  = (const float*)d_in[5];
    const float* b1  = (const float*)d_in[6];
    const float* w2  = (const float*)d_in[7];
    const float* b2  = (const float*)d_in[8];
    const float* w3  = (const float*)d_in[9];
    const float* b3  = (const float*)d_in[10];
    float* out = (float*)d_out;

    const size_t sm2  = (size_t)(NH * NE + 16 + 128 * 65) * sizeof(float);
    const int    smm  = 2 * STG_BYTES;   // 128 KB double-buffered stages
    cudaFuncSetAttribute(gate_route_kernel, cudaFuncAttributeMaxDynamicSharedMemorySize, (int)sm2);
    cudaFuncSetAttribute(mma_kernel<1, DIN, NH>,  cudaFuncAttributeMaxDynamicSharedMemorySize, smm);
    cudaFuncSetAttribute(mma_kernel<2, NH, NH>,   cudaFuncAttributeMaxDynamicSharedMemorySize, smm);
    cudaFuncSetAttribute(mma_kernel<3, NH, DOUT>, cudaFuncAttributeMaxDynamicSharedMemorySize, smm);

    cudaMemsetAsync(out, 0, (size_t)NTOK * DOUT * sizeof(float));
    zero_cnt_kernel<<<1, 32>>>();
    split_x_kernel<<<NTOK * DIN / 2 / 256, 256>>>(x);
    transpose_split_kernel<1><<<dim3(NH / 32, DIN / 32, NE), dim3(32, 8)>>>(w1, NH,   (long)NE * NH,   DIN, NH);
    transpose_split_kernel<2><<<dim3(NH / 32, NH / 32, NE),  dim3(32, 8)>>>(w2, NH,   (long)NE * NH,   NH,  NH);
    transpose_split_kernel<3><<<dim3(DOUT / 32, NH / 32, NE), dim3(32, 8)>>>(w3, DOUT, (long)NE * DOUT, NH,  DOUT);
    gate_h_kernel<<<NTOK / 32, 256>>>(x, gw, gb);
    gate_route_kernel<<<NTOK / 128, 128, sm2>>>(gow, gob);
    prefix_kernel<<<1, 32>>>();
    mma_kernel<1, DIN, NH><<<dim3(64, NE, 4), 256, smm>>>(b1, nullptr);
    mma_kernel<2, NH, NH><<<dim3(64, NE, 4), 256, smm>>>(b2, nullptr);
    mma_kernel<3, NH, DOUT><<<dim3(64, NE, 2), 256, smm>>>(b3, out);
}

// round 7
// speedup vs baseline: 3.8404x; 1.0209x over previous
#include <cuda_runtime.h>
#include <cuda_bf16.h>
#include <cstdint>

#define NTOK 8192
#define DIN  256
#define DOUT 256
#define NE   16
#define NH   512
#define SLOTS 18560   // >= 16384 + 16*127 padded routed slots

// ---------------------------------------------------------------------------
// Device scratch
// ---------------------------------------------------------------------------
__device__ float g_Hg[NTOK * NH];          // gating hidden (fp32)
__device__ int   g_cnt[NE];
__device__ int   g_off[NE];                // padded prefix offsets
__device__ int   g_rtok[NE * NTOK];
__device__ float g_rgate[NE * NTOK];

__device__ __nv_bfloat16 g_xhi[NTOK * DIN],  g_xlo[NTOK * DIN];
__device__ __nv_bfloat16 g_w1Thi[NE * NH * DIN],  g_w1Tlo[NE * NH * DIN];    // [e][n=512][k=256]
__device__ __nv_bfloat16 g_w2Thi[NE * NH * NH],   g_w2Tlo[NE * NH * NH];     // [e][512][512]
__device__ __nv_bfloat16 g_w3Thi[NE * DOUT * NH], g_w3Tlo[NE * DOUT * NH];   // [e][256][512]
__device__ __nv_bfloat16 g_h1hi[(size_t)SLOTS * NH], g_h1lo[(size_t)SLOTS * NH];
__device__ __nv_bfloat16 g_h2hi[(size_t)SLOTS * NH], g_h2lo[(size_t)SLOTS * NH];

// ---------------------------------------------------------------------------
// PTX helpers (compute_103-safe: cp.async + ldmatrix + mma.sync only)
// ---------------------------------------------------------------------------
__device__ __forceinline__ uint32_t smem_u32(const void* p) {
    uint32_t a;
    asm("{ .reg .u64 t; cvta.to.shared.u64 t, %1; cvt.u32.u64 %0, t; }" : "=r"(a) : "l"(p));
    return a;
}
#define CP16(dst, src) \
    asm volatile("cp.async.cg.shared.global [%0], [%1], 16;" :: "r"(dst), "l"(src) : "memory")
#define CP_COMMIT() asm volatile("cp.async.commit_group;" ::: "memory")
#define CP_WAIT(n)  asm volatile("cp.async.wait_group %0;" :: "n"(n) : "memory")

#define LDSM4(r, addr) \
    asm volatile("ldmatrix.sync.aligned.m8n8.x4.shared.b16 {%0,%1,%2,%3}, [%4];" \
        : "=r"((r)[0]), "=r"((r)[1]), "=r"((r)[2]), "=r"((r)[3]) : "r"(addr))

#define MMA16816(c, a, b) \
    asm volatile("mma.sync.aligned.m16n8k16.row.col.f32.bf16.bf16.f32 " \
        "{%0,%1,%2,%3}, {%4,%5,%6,%7}, {%8,%9}, {%0,%1,%2,%3};" \
        : "+f"((c)[0]), "+f"((c)[1]), "+f"((c)[2]), "+f"((c)[3]) \
        : "r"((a)[0]), "r"((a)[1]), "r"((a)[2]), "r"((a)[3]), "r"((b)[0]), "r"((b)[1]))

// Packed fp32x2 helpers (gate path)
#define FMA2(d, a, b) asm("fma.rn.f32x2 %0, %1, %2, %0;" : "+l"(d) : "l"(a), "l"(b))
#define DUP2(d, s)    asm("mov.b64 %0, {%1, %1};" : "=l"(d) : "f"(s))
#define UNPK(lo, hi, s) asm("mov.b64 {%0, %1}, %2;" : "=f"(lo), "=f"(hi) : "l"(s))

// ---------------------------------------------------------------------------
// Small prep kernels
// ---------------------------------------------------------------------------
__global__ void zero_cnt_kernel() {
    if (threadIdx.x < NE) g_cnt[threadIdx.x] = 0;
}
__global__ void prefix_kernel() {
    if (threadIdx.x == 0) {
        int off = 0;
        for (int e = 0; e < NE; ++e) {
            g_off[e] = off;
            off += ((g_cnt[e] + 127) >> 7) << 7;
        }
    }
}
__global__ void split_x_kernel(const float* __restrict__ x) {
    int i = blockIdx.x * blockDim.x + threadIdx.x;   // pair index
    float2 v = ((const float2*)x)[i];
    __nv_bfloat16 h0 = __float2bfloat16(v.x), h1 = __float2bfloat16(v.y);
    float r0 = v.x - __bfloat162float(h0), r1 = v.y - __bfloat162float(h1);
    __nv_bfloat16 l0 = __float2bfloat16(r0), l1 = __float2bfloat16(r1);
    ((uint32_t*)g_xhi)[i] = (uint32_t)__bfloat16_as_ushort(h0) | ((uint32_t)__bfloat16_as_ushort(h1) << 16);
    ((uint32_t*)g_xlo)[i] = (uint32_t)__bfloat16_as_ushort(l0) | ((uint32_t)__bfloat16_as_ushort(l1) << 16);
}

// Transpose + split: W[k][n] (row stride rs, per-expert col base e_off) -> planes [n][k]
template<int WID>
__global__ void transpose_split_kernel(const float* __restrict__ src,
                                       int e_off, long rs, int K, int N)
{
    __shared__ float t[32][33];
    const int e = blockIdx.z;
    const int n0 = blockIdx.x * 32, k0 = blockIdx.y * 32;
    const int tx = threadIdx.x, ty = threadIdx.y;
    const float* s = src + (long)e * e_off;
#pragma unroll
    for (int i = 0; i < 4; ++i)
        t[ty + 8 * i][tx] = s[(long)(k0 + ty + 8 * i) * rs + n0 + tx];
    __syncthreads();
    __nv_bfloat16* dh = (WID == 1) ? g_w1Thi : (WID == 2) ? g_w2Thi : g_w3Thi;
    __nv_bfloat16* dl = (WID == 1) ? g_w1Tlo : (WID == 2) ? g_w2Tlo : g_w3Tlo;
    dh += (size_t)e * N * K;  dl += (size_t)e * N * K;
#pragma unroll
    for (int i = 0; i < 4; ++i) {
        float v = t[tx][ty + 8 * i];
        __nv_bfloat16 h = __float2bfloat16(v);
        float r = v - __bfloat162float(h);
        size_t idx = (size_t)(n0 + ty + 8 * i) * K + k0 + tx;
        dh[idx] = h;
        dl[idx] = __float2bfloat16(r);
    }
}

// ---------------------------------------------------------------------------
// Gate hidden (scalar fp32, FFMA2) — kept exact so routing matches reference
// ---------------------------------------------------------------------------
__device__ __forceinline__ void load_tileT(
    float* __restrict__ St, const float* __restrict__ x,
    const int* __restrict__ toks, int m, int tid)
{
    const int wid = tid >> 5, lane = tid & 31;
    const int fb = wid * 32;
    float v[32];
#pragma unroll
    for (int r = 0; r < 32; ++r)
        v[r] = (r < m) ? x[(long)toks[r] * DIN + fb + lane] : 0.f;
#pragma unroll
    for (int rr = 0; rr < 32; ++rr) {
        int r = (rr + lane) & 31;
        St[(fb + lane) * 32 + r] = v[r];
    }
}

template<int KDIM>
__device__ __forceinline__ void gemm_coreT(
    const float* __restrict__ St, const float* __restrict__ W, long ws,
    int c0, int c1, unsigned long long* accA, unsigned long long* accB)
{
#pragma unroll 2
    for (int k = 0; k < KDIM; k += 4) {
        const float* wp = W + (long)k * ws;
        unsigned long long ua[4], ub[4];
#pragma unroll
        for (int j = 0; j < 4; ++j) {
            float wa = wp[(long)j * ws + c0];
            float wb = wp[(long)j * ws + c1];
            DUP2(ua[j], wa); DUP2(ub[j], wb);
        }
#pragma unroll
        for (int j = 0; j < 4; ++j) {
            const ulonglong2* xp = (const ulonglong2*)(St + (k + j) * 32);
#pragma unroll
            for (int p = 0; p < 8; ++p) {
                ulonglong2 X = xp[p];
                FMA2(accA[2 * p],     X.x, ua[j]);
                FMA2(accA[2 * p + 1], X.y, ua[j]);
                FMA2(accB[2 * p],     X.x, ub[j]);
                FMA2(accB[2 * p + 1], X.y, ub[j]);
            }
        }
    }
}

__global__ __launch_bounds__(256, 2) void gate_h_kernel(
    const float* __restrict__ x, const float* __restrict__ gw, const float* __restrict__ gb)
{
    __shared__ __align__(16) float Xs[DIN * 32];
    __shared__ int toks[32];
    const int tid = threadIdx.x;
    const int t0 = blockIdx.x * 32;
    if (tid < 32) toks[tid] = t0 + tid;
    __syncthreads();
    load_tileT(Xs, x, toks, 32, tid);
    __syncthreads();

    const int c0 = tid, c1 = tid + 256;
    unsigned long long accA[16], accB[16];
    float bb0 = gb[c0], bb1 = gb[c1];
#pragma unroll
    for (int p = 0; p < 16; ++p) { DUP2(accA[p], bb0); DUP2(accB[p], bb1); }
    gemm_coreT<DIN>(Xs, gw, NH, c0, c1, accA, accB);
#pragma unroll
    for (int p = 0; p < 16; ++p) {
        float lo, hi;
        UNPK(lo, hi, accA[p]);
        g_Hg[(long)(t0 + 2 * p) * NH + c0]     = fmaxf(lo, 0.f);
        g_Hg[(long)(t0 + 2 * p + 1) * NH + c0] = fmaxf(hi, 0.f);
        UNPK(lo, hi, accB[p]);
        g_Hg[(long)(t0 + 2 * p) * NH + c1]     = fmaxf(lo, 0.f);
        g_Hg[(long)(t0 + 2 * p + 1) * NH + c1] = fmaxf(hi, 0.f);
    }
}

// ---------------------------------------------------------------------------
// Routing (unchanged, fp32-exact)
// ---------------------------------------------------------------------------
__global__ __launch_bounds__(128) void gate_route_kernel(
    const float* __restrict__ gow, const float* __restrict__ gob)
{
    extern __shared__ float sm2[];
    float* Gw = sm2;
    float* Gb = Gw + NH * NE;
    float* Ht = Gb + 16;

    const int tid = threadIdx.x;
    for (int idx = tid; idx < NH * NE; idx += 128) Gw[idx] = gow[idx];
    if (tid < NE) Gb[tid] = gob[tid];

    const int tok0 = blockIdx.x * 128;
    float acc[NE];
#pragma unroll
    for (int e = 0; e < NE; ++e) acc[e] = 0.f;

    for (int hb = 0; hb < NH; hb += 64) {
        __syncthreads();
        for (int idx = tid; idx < 128 * 64; idx += 128) {
            int r = idx >> 6, h = idx & 63;
            Ht[r * 65 + h] = g_Hg[(long)(tok0 + r) * NH + hb + h];
        }
        __syncthreads();
#pragma unroll 8
        for (int hl = 0; hl < 64; ++hl) {
            float v = Ht[tid * 65 + hl];
            const float4* gp = (const float4*)(Gw + (hb + hl) * NE);
            float4 g0v = gp[0], g1v = gp[1], g2v = gp[2], g3v = gp[3];
            acc[0]  = fmaf(v, g0v.x, acc[0]);   acc[1]  = fmaf(v, g0v.y, acc[1]);
            acc[2]  = fmaf(v, g0v.z, acc[2]);   acc[3]  = fmaf(v, g0v.w, acc[3]);
            acc[4]  = fmaf(v, g1v.x, acc[4]);   acc[5]  = fmaf(v, g1v.y, acc[5]);
            acc[6]  = fmaf(v, g1v.z, acc[6]);   acc[7]  = fmaf(v, g1v.w, acc[7]);
            acc[8]  = fmaf(v, g2v.x, acc[8]);   acc[9]  = fmaf(v, g2v.y, acc[9]);
            acc[10] = fmaf(v, g2v.z, acc[10]);  acc[11] = fmaf(v, g2v.w, acc[11]);
            acc[12] = fmaf(v, g3v.x, acc[12]);  acc[13] = fmaf(v, g3v.y, acc[13]);
            acc[14] = fmaf(v, g3v.z, acc[14]);  acc[15] = fmaf(v, g3v.w, acc[15]);
        }
    }

    float v0 = -1e30f, v1 = -1e30f;
    int i0 = 0, i1 = 0;
#pragma unroll
    for (int e = 0; e < NE; ++e) {
        float l = acc[e] + Gb[e];
        if (l > v0)      { v1 = v0; i1 = i0; v0 = l; i0 = e; }
        else if (l > v1) { v1 = l;  i1 = e; }
    }
    float e1 = __expf(v1 - v0);
    float s  = 1.f + e1;
    float ga = 1.f / s;
    float gb2 = e1 / s;

    const int tok = tok0 + tid;
    int p0 = atomicAdd(&g_cnt[i0], 1);
    g_rtok[i0 * NTOK + p0]  = tok;
    g_rgate[i0 * NTOK + p0] = ga;
    int p1 = atomicAdd(&g_cnt[i1], 1);
    g_rtok[i1 * NTOK + p1]  = tok;
    g_rgate[i1 * NTOK + p1] = gb2;
}

// ---------------------------------------------------------------------------
// HMMA split-bf16 GEMM. MODE 1: X->H1, 2: H1->H2, 3: H2->out (gated scatter)
// CTA: 128 M-slots x 128 N-cols, K chunked by 64, 2-stage cp.async pipeline.
// 8 warps = 4(M) x 2(N); warp tile 32x64; mma.sync m16n8k16 bf16.
// smem stage: Ahi | Alo | Bhi | Blo, 16KB each (swizzled [row][64] bf16).
// B stored [n][k] -> plain ldmatrix (NO trans) yields col-major B frags.
// ---------------------------------------------------------------------------
#define STG_BYTES 65536

template<int MODE, int KF, int NW>
__global__ __launch_bounds__(256, 1) void mma_kernel(
    const float* __restrict__ bias, float* __restrict__ outp)
{
    const int e    = blockIdx.y;
    const int tile = blockIdx.x;
    const int cnt  = g_cnt[e];
    if (tile * 128 >= cnt) return;
    const int nbase = blockIdx.z * 128;
    const int m = min(128, cnt - tile * 128);
    const int slotbase = g_off[e] + tile * 128;

    const __nv_bfloat16* Ahip = (MODE == 1) ? g_xhi : (MODE == 2) ? g_h1hi : g_h2hi;
    const __nv_bfloat16* Alop = (MODE == 1) ? g_xlo : (MODE == 2) ? g_h1lo : g_h2lo;
    const __nv_bfloat16* Bhi_e = ((MODE == 1) ? g_w1Thi : (MODE == 2) ? g_w2Thi : g_w3Thi)
                                 + (size_t)e * NW * KF;
    const __nv_bfloat16* Blo_e = ((MODE == 1) ? g_w1Tlo : (MODE == 2) ? g_w2Tlo : g_w3Tlo)
                                 + (size_t)e * NW * KF;
    __nv_bfloat16* Ohi = (MODE == 1) ? g_h1hi : g_h2hi;
    __nv_bfloat16* Olo = (MODE == 1) ? g_h1lo : g_h2lo;

    extern __shared__ char smp[];
    const uint32_t smb = smem_u32(smp);
    __shared__ int   toks[128];
    __shared__ float gts[128];
    __shared__ float sbias[128];

    const int tid  = threadIdx.x;
    const int wid  = tid >> 5, lane = tid & 31;
    const int wm   = wid & 3,  wn   = wid >> 2;

    if (tid < 128) {
        if (MODE != 2) {
            int i = tile * 128 + tid;
            bool v = (i < cnt);
            toks[tid] = v ? g_rtok[e * NTOK + i] : 0;
            gts[tid]  = v ? g_rgate[e * NTOK + i] : 0.f;
        }
        sbias[tid] = bias[e * NW + nbase + tid];
    }
    __syncthreads();

    const int NCH = KF / 64;

    // ---- async chunk loader: 16 cp.async of 16B per thread ----
    auto load_chunk = [&](int ch, int s) {
        const int kbase = ch * 64;
        const uint32_t sb = smb + s * STG_BYTES;
#pragma unroll
        for (int i = 0; i < 4; ++i) {
            int idx = tid + i * 256;          // 0..1023
            int row = idx >> 3, u = idx & 7;
            uint32_t d = sb + row * 128 + ((u ^ (row & 7)) << 4);
            long arow = (MODE == 1) ? (long)toks[row] : (long)(slotbase + row);
            const __nv_bfloat16* sa = Ahip + arow * KF + kbase + u * 8;
            CP16(d, sa);
            CP16(d + 16384, Alop + arow * KF + kbase + u * 8);
            const __nv_bfloat16* sbp = Bhi_e + (size_t)(nbase + row) * KF + kbase + u * 8;
            CP16(d + 32768, sbp);
            CP16(d + 49152, Blo_e + (size_t)(nbase + row) * KF + kbase + u * 8);
        }
        CP_COMMIT();
    };

    float acc[2][8][4];
#pragma unroll
    for (int mf = 0; mf < 2; ++mf)
#pragma unroll
        for (int nf = 0; nf < 8; ++nf)
#pragma unroll
            for (int j = 0; j < 4; ++j) acc[mf][nf][j] = 0.f;

    load_chunk(0, 0);

    for (int ch = 0; ch < NCH; ++ch) {
        if (ch + 1 < NCH) { load_chunk(ch + 1, (ch + 1) & 1); CP_WAIT(1); }
        else              { CP_WAIT(0); }
        __syncthreads();

        const uint32_t sb  = smb + (ch & 1) * STG_BYTES;
        const uint32_t aHI = sb, aLO = sb + 16384, bHI = sb + 32768, bLO = sb + 49152;

#pragma unroll
        for (int ks = 0; ks < 4; ++ks) {
            const int k0 = ks * 16;
            // A fragments (row-major 16x16 via ldmatrix.x4)
            uint32_t ahi[2][4], alo[2][4];
            {
                int r_ = (lane & 7) + ((lane >> 3) & 1) * 8;
                int ak = k0 + (lane >> 4) * 8;
#pragma unroll
                for (int mf = 0; mf < 2; ++mf) {
                    int r = wm * 32 + mf * 16 + r_;
                    uint32_t off = (uint32_t)(r * 128 + ((((ak >> 3) ^ (r & 7))) << 4));
                    LDSM4(ahi[mf], aHI + off);
                    LDSM4(alo[mf], aLO + off);
                }
            }
            // B fragments: [n][k] storage, plain ldmatrix on n-rows -> col-major frags
            uint32_t bhi[8][2], blo[8][2];
            {
                int n_ = (lane & 7) + (lane >> 4) * 8;
                int bk = k0 + ((lane >> 3) & 1) * 8;
#pragma unroll
                for (int nb = 0; nb < 4; ++nb) {
                    int n = wn * 64 + nb * 16 + n_;
                    uint32_t off = (uint32_t)(n * 128 + ((((bk >> 3) ^ (n & 7))) << 4));
                    uint32_t r4[4];
                    LDSM4(r4, bHI + off);
                    bhi[2 * nb][0] = r4[0]; bhi[2 * nb][1] = r4[1];
                    bhi[2 * nb + 1][0] = r4[2]; bhi[2 * nb + 1][1] = r4[3];
                    LDSM4(r4, bLO + off);
                    blo[2 * nb][0] = r4[0]; blo[2 * nb][1] = r4[1];
                    blo[2 * nb + 1][0] = r4[2]; blo[2 * nb + 1][1] = r4[3];
                }
            }
            // 3 split-products, interleaved so same-acc chains are 16 apart
#pragma unroll
            for (int mf = 0; mf < 2; ++mf)
#pragma unroll
                for (int nf = 0; nf < 8; ++nf) MMA16816(acc[mf][nf], ahi[mf], bhi[nf]);
#pragma unroll
            for (int mf = 0; mf < 2; ++mf)
#pragma unroll
                for (int nf = 0; nf < 8; ++nf) MMA16816(acc[mf][nf], alo[mf], bhi[nf]);
#pragma unroll
            for (int mf = 0; mf < 2; ++mf)
#pragma unroll
                for (int nf = 0; nf < 8; ++nf) MMA16816(acc[mf][nf], ahi[mf], blo[nf]);
        }
        __syncthreads();   // all warps done reading before stage is overwritten
    }

    // ---- epilogue ----
    const int grp = lane >> 2, t2 = (lane & 3) * 2;
#pragma unroll
    for (int mf = 0; mf < 2; ++mf) {
#pragma unroll
        for (int nf = 0; nf < 8; ++nf) {
            const float* c = acc[mf][nf];
            const int col = wn * 64 + nf * 8 + t2;        // 0..127 in-tile
#pragma unroll
            for (int half = 0; half < 2; ++half) {
                const int r = wm * 32 + mf * 16 + grp + half * 8;
                float v0 = c[half * 2 + 0] + sbias[col];
                float v1 = c[half * 2 + 1] + sbias[col + 1];
                if (MODE == 3) {
                    if (r < m) {
                        float g = gts[r];
                        float* orow = outp + (size_t)toks[r] * DOUT + nbase + col;
                        atomicAdd(orow,     g * v0);
                        atomicAdd(orow + 1, g * v1);
                    }
                } else {
                    v0 = fmaxf(v0, 0.f);
                    v1 = fmaxf(v1, 0.f);
                    __nv_bfloat16 h0 = __float2bfloat16(v0), h1 = __float2bfloat16(v1);
                    float r0 = v0 - __bfloat162float(h0), r1 = v1 - __bfloat162float(h1);
                    __nv_bfloat16 l0 = __float2bfloat16(r0), l1 = __float2bfloat16(r1);
                    size_t oi = (size_t)(slotbase + r) * NH + nbase + col;
                    *(uint32_t*)(Ohi + oi) =
                        (uint32_t)__bfloat16_as_ushort(h0) | ((uint32_t)__bfloat16_as_ushort(h1) << 16);
                    *(uint32_t*)(Olo + oi) =
                        (uint32_t)__bfloat16_as_ushort(l0) | ((uint32_t)__bfloat16_as_ushort(l1) << 16);
                }
            }
        }
    }
}

// ---------------------------------------------------------------------------
extern "C" void kernel_launch(void* const* d_in, const int* in_sizes, int n_in,
                              void* d_out, int out_size)
{
    const float* x   = (const float*)d_in[0];
    const float* gw  = (const float*)d_in[1];
    const float* gb  = (const float*)d_in[2];
    const float* gow = (const float*)d_in[3];
    const float* gob = (const float*)d_in[4];
    const float* w1  = (const float*)d_in[5];
    const float* b1  = (const float*)d_in[6];
    const float* w2  = (const float*)d_in[7];
    const float* b2  = (const float*)d_in[8];
    const float* w3  = (const float*)d_in[9];
    const float* b3  = (const float*)d_in[10];
    float* out = (float*)d_out;

    // One-time host resources (created on the first, uncaptured correctness
    // call; reused verbatim during graph capture — events become graph edges).
    static cudaStream_t s_side = nullptr;
    static cudaEvent_t  s_evF = nullptr, s_evJ = nullptr;
    if (!s_side) {
        cudaStreamCreateWithFlags(&s_side, cudaStreamNonBlocking);
        cudaEventCreateWithFlags(&s_evF, cudaEventDisableTiming);
        cudaEventCreateWithFlags(&s_evJ, cudaEventDisableTiming);
    }

    const size_t sm2  = (size_t)(NH * NE + 16 + 128 * 65) * sizeof(float);
    const int    smm  = 2 * STG_BYTES;   // 128 KB double-buffered stages
    cudaFuncSetAttribute(gate_route_kernel, cudaFuncAttributeMaxDynamicSharedMemorySize, (int)sm2);
    cudaFuncSetAttribute(mma_kernel<1, DIN, NH>,  cudaFuncAttributeMaxDynamicSharedMemorySize, smm);
    cudaFuncSetAttribute(mma_kernel<2, NH, NH>,   cudaFuncAttributeMaxDynamicSharedMemorySize, smm);
    cudaFuncSetAttribute(mma_kernel<3, NH, DOUT>, cudaFuncAttributeMaxDynamicSharedMemorySize, smm);

    // ---- fork: side branch = prep (independent of gate path) ----
    cudaEventRecord(s_evF, 0);
    cudaStreamWaitEvent(s_side, s_evF, 0);

    cudaMemsetAsync(out, 0, (size_t)NTOK * DOUT * sizeof(float), s_side);
    split_x_kernel<<<NTOK * DIN / 2 / 256, 256, 0, s_side>>>(x);
    transpose_split_kernel<1><<<dim3(NH / 32, DIN / 32, NE), dim3(32, 8), 0, s_side>>>(
        w1, NH, (long)NE * NH, DIN, NH);
    transpose_split_kernel<2><<<dim3(NH / 32, NH / 32, NE), dim3(32, 8), 0, s_side>>>(
        w2, NH, (long)NE * NH, NH, NH);
    transpose_split_kernel<3><<<dim3(DOUT / 32, NH / 32, NE), dim3(32, 8), 0, s_side>>>(
        w3, DOUT, (long)NE * DOUT, NH, DOUT);

    // ---- main branch = gate path ----
    zero_cnt_kernel<<<1, 32>>>();
    gate_h_kernel<<<NTOK / 32, 256>>>(x, gw, gb);
    gate_route_kernel<<<NTOK / 128, 128, sm2>>>(gow, gob);
    prefix_kernel<<<1, 32>>>();

    // ---- join ----
    cudaEventRecord(s_evJ, s_side);
    cudaStreamWaitEvent(0, s_evJ, 0);

    mma_kernel<1, DIN, NH><<<dim3(64, NE, 4), 256, smm>>>(b1, nullptr);
    mma_kernel<2, NH, NH><<<dim3(64, NE, 4), 256, smm>>>(b2, nullptr);
    mma_kernel<3, NH, DOUT><<<dim3(64, NE, 2), 256, smm>>>(b3, out);
}

// round 8
// speedup vs baseline: 4.5556x; 1.1862x over previous
#include <cuda_runtime.h>
#include <cuda_bf16.h>
#include <cstdint>

#define NTOK 8192
#define DIN  256
#define DOUT 256
#define NE   16
#define NH   512
#define SLOTS 18560   // >= 16384 + 16*127 padded routed slots

// ---------------------------------------------------------------------------
// Device scratch
// ---------------------------------------------------------------------------
__device__ int   g_cnt[NE];
__device__ int   g_off[NE];                // padded prefix offsets
__device__ int   g_rtok[NE * NTOK];
__device__ float g_rgate[NE * NTOK];

__device__ __nv_bfloat16 g_xhi[NTOK * DIN],  g_xlo[NTOK * DIN];
__device__ __nv_bfloat16 g_w1Thi[NE * NH * DIN],  g_w1Tlo[NE * NH * DIN];    // [e][n=512][k=256]
__device__ __nv_bfloat16 g_w2Thi[NE * NH * NH],   g_w2Tlo[NE * NH * NH];     // [e][512][512]
__device__ __nv_bfloat16 g_w3Thi[NE * DOUT * NH], g_w3Tlo[NE * DOUT * NH];   // [e][256][512]
__device__ __nv_bfloat16 g_h1hi[(size_t)SLOTS * NH], g_h1lo[(size_t)SLOTS * NH];
__device__ __nv_bfloat16 g_h2hi[(size_t)SLOTS * NH], g_h2lo[(size_t)SLOTS * NH];

// ---------------------------------------------------------------------------
// PTX helpers (compute_103-safe: cp.async + ldmatrix + mma.sync only)
// ---------------------------------------------------------------------------
__device__ __forceinline__ uint32_t smem_u32(const void* p) {
    uint32_t a;
    asm("{ .reg .u64 t; cvta.to.shared.u64 t, %1; cvt.u32.u64 %0, t; }" : "=r"(a) : "l"(p));
    return a;
}
#define CP16(dst, src) \
    asm volatile("cp.async.cg.shared.global [%0], [%1], 16;" :: "r"(dst), "l"(src) : "memory")
#define CP_COMMIT() asm volatile("cp.async.commit_group;" ::: "memory")
#define CP_WAIT(n)  asm volatile("cp.async.wait_group %0;" :: "n"(n) : "memory")

#define LDSM4(r, addr) \
    asm volatile("ldmatrix.sync.aligned.m8n8.x4.shared.b16 {%0,%1,%2,%3}, [%4];" \
        : "=r"((r)[0]), "=r"((r)[1]), "=r"((r)[2]), "=r"((r)[3]) : "r"(addr))

#define MMA16816(c, a, b) \
    asm volatile("mma.sync.aligned.m16n8k16.row.col.f32.bf16.bf16.f32 " \
        "{%0,%1,%2,%3}, {%4,%5,%6,%7}, {%8,%9}, {%0,%1,%2,%3};" \
        : "+f"((c)[0]), "+f"((c)[1]), "+f"((c)[2]), "+f"((c)[3]) \
        : "r"((a)[0]), "r"((a)[1]), "r"((a)[2]), "r"((a)[3]), "r"((b)[0]), "r"((b)[1]))

// Packed fp32x2 helpers (gate path)
#define FMA2(d, a, b) asm("fma.rn.f32x2 %0, %1, %2, %0;" : "+l"(d) : "l"(a), "l"(b))
#define DUP2(d, s)    asm("mov.b64 %0, {%1, %1};" : "=l"(d) : "f"(s))
#define UNPK(lo, hi, s) asm("mov.b64 {%0, %1}, %2;" : "=f"(lo), "=f"(hi) : "l"(s))

// ---------------------------------------------------------------------------
// Small prep kernels
// ---------------------------------------------------------------------------
__global__ void zero_cnt_kernel() {
    if (threadIdx.x < NE) g_cnt[threadIdx.x] = 0;
}
__global__ void prefix_kernel() {
    if (threadIdx.x == 0) {
        int off = 0;
        for (int e = 0; e < NE; ++e) {
            g_off[e] = off;
            off += ((g_cnt[e] + 127) >> 7) << 7;
        }
    }
}
__global__ void split_x_kernel(const float* __restrict__ x) {
    int i = blockIdx.x * blockDim.x + threadIdx.x;   // pair index
    float2 v = ((const float2*)x)[i];
    __nv_bfloat16 h0 = __float2bfloat16(v.x), h1 = __float2bfloat16(v.y);
    float r0 = v.x - __bfloat162float(h0), r1 = v.y - __bfloat162float(h1);
    __nv_bfloat16 l0 = __float2bfloat16(r0), l1 = __float2bfloat16(r1);
    ((uint32_t*)g_xhi)[i] = (uint32_t)__bfloat16_as_ushort(h0) | ((uint32_t)__bfloat16_as_ushort(h1) << 16);
    ((uint32_t*)g_xlo)[i] = (uint32_t)__bfloat16_as_ushort(l0) | ((uint32_t)__bfloat16_as_ushort(l1) << 16);
}

// Transpose + split: W[k][n] (row stride rs, per-expert col base e_off) -> planes [n][k]
template<int WID>
__global__ void transpose_split_kernel(const float* __restrict__ src,
                                       int e_off, long rs, int K, int N)
{
    __shared__ float t[32][33];
    const int e = blockIdx.z;
    const int n0 = blockIdx.x * 32, k0 = blockIdx.y * 32;
    const int tx = threadIdx.x, ty = threadIdx.y;
    const float* s = src + (long)e * e_off;
#pragma unroll
    for (int i = 0; i < 4; ++i)
        t[ty + 8 * i][tx] = s[(long)(k0 + ty + 8 * i) * rs + n0 + tx];
    __syncthreads();
    __nv_bfloat16* dh = (WID == 1) ? g_w1Thi : (WID == 2) ? g_w2Thi : g_w3Thi;
    __nv_bfloat16* dl = (WID == 1) ? g_w1Tlo : (WID == 2) ? g_w2Tlo : g_w3Tlo;
    dh += (size_t)e * N * K;  dl += (size_t)e * N * K;
#pragma unroll
    for (int i = 0; i < 4; ++i) {
        float v = t[tx][ty + 8 * i];
        __nv_bfloat16 h = __float2bfloat16(v);
        float r = v - __bfloat162float(h);
        size_t idx = (size_t)(n0 + ty + 8 * i) * K + k0 + tx;
        dh[idx] = h;
        dl[idx] = __float2bfloat16(r);
    }
}

// ---------------------------------------------------------------------------
// Fused gate kernel: hidden GEMM (fp32 FFMA2, exact) + logits + top-2 +
// softmax + routing append, all in one kernel. 32 tokens per CTA.
// ---------------------------------------------------------------------------
template<int KDIM>
__device__ __forceinline__ void gemm_coreT(
    const float* __restrict__ St, const float* __restrict__ W, long ws,
    int c0, int c1, unsigned long long* accA, unsigned long long* accB)
{
#pragma unroll 2
    for (int k = 0; k < KDIM; k += 4) {
        const float* wp = W + (long)k * ws;
        unsigned long long ua[4], ub[4];
#pragma unroll
        for (int j = 0; j < 4; ++j) {
            float wa = wp[(long)j * ws + c0];
            float wb = wp[(long)j * ws + c1];
            DUP2(ua[j], wa); DUP2(ub[j], wb);
        }
#pragma unroll
        for (int j = 0; j < 4; ++j) {
            const ulonglong2* xp = (const ulonglong2*)(St + (k + j) * 32);
#pragma unroll
            for (int p = 0; p < 8; ++p) {
                ulonglong2 X = xp[p];
                FMA2(accA[2 * p],     X.x, ua[j]);
                FMA2(accA[2 * p + 1], X.y, ua[j]);
                FMA2(accB[2 * p],     X.x, ub[j]);
                FMA2(accB[2 * p + 1], X.y, ub[j]);
            }
        }
    }
}

#define HPAD 513
#define GPAD 20

__global__ __launch_bounds__(256) void gate_fused_kernel(
    const float* __restrict__ x,  const float* __restrict__ gw,
    const float* __restrict__ gb, const float* __restrict__ gow,
    const float* __restrict__ gob)
{
    extern __shared__ __align__(16) float dynsm[];
    float* Xs  = dynsm;                        // [256][32] transposed x tile
    float* hS  = dynsm + 8192;                 // [32][HPAD]
    float* gwS = dynsm + 8192 + 32 * HPAD;     // [512][GPAD]

    const int tid = threadIdx.x;
    const int wid = tid >> 5, lane = tid & 31;
    const int t0 = blockIdx.x * 32;

    // load x tile transposed [k][r], lane-rotated stores (conflict-free)
    {
        const int fb = wid * 32;
        float v[32];
#pragma unroll
        for (int r = 0; r < 32; ++r)
            v[r] = x[(long)(t0 + r) * DIN + fb + lane];
#pragma unroll
        for (int rr = 0; rr < 32; ++rr) {
            int r = (rr + lane) & 31;
            Xs[(fb + lane) * 32 + r] = v[r];
        }
    }
    __syncthreads();

    const int c0 = tid, c1 = tid + 256;
    unsigned long long accA[16], accB[16];
    float bb0 = gb[c0], bb1 = gb[c1];
#pragma unroll
    for (int p = 0; p < 16; ++p) { DUP2(accA[p], bb0); DUP2(accB[p], bb1); }
    gemm_coreT<DIN>(Xs, gw, NH, c0, c1, accA, accB);

    // write relu'd hidden to smem [token][col]
#pragma unroll
    for (int p = 0; p < 16; ++p) {
        float lo, hi;
        UNPK(lo, hi, accA[p]);
        hS[(2 * p) * HPAD + c0]     = fmaxf(lo, 0.f);
        hS[(2 * p + 1) * HPAD + c0] = fmaxf(hi, 0.f);
        UNPK(lo, hi, accB[p]);
        hS[(2 * p) * HPAD + c1]     = fmaxf(lo, 0.f);
        hS[(2 * p + 1) * HPAD + c1] = fmaxf(hi, 0.f);
    }
    // load gate_out_w into padded smem
    for (int idx = tid; idx < NH * NE; idx += 256) {
        int r = idx >> 4, c = idx & 15;
        gwS[r * GPAD + c] = gow[idx];
    }
    __syncthreads();

    // logits: 8 threads per token, each covers h indices {s, s+8, ..., s+504}
    const int t = tid >> 3, s = tid & 7;
    float l[NE];
#pragma unroll
    for (int e = 0; e < NE; ++e) l[e] = 0.f;
#pragma unroll 4
    for (int i = 0; i < 64; ++i) {
        int hidx = s + 8 * i;
        float v = hS[t * HPAD + hidx];
        const float4* gp = (const float4*)(gwS + hidx * GPAD);
        float4 a = gp[0], b = gp[1], c4 = gp[2], d = gp[3];
        l[0]  = fmaf(v, a.x,  l[0]);   l[1]  = fmaf(v, a.y,  l[1]);
        l[2]  = fmaf(v, a.z,  l[2]);   l[3]  = fmaf(v, a.w,  l[3]);
        l[4]  = fmaf(v, b.x,  l[4]);   l[5]  = fmaf(v, b.y,  l[5]);
        l[6]  = fmaf(v, b.z,  l[6]);   l[7]  = fmaf(v, b.w,  l[7]);
        l[8]  = fmaf(v, c4.x, l[8]);   l[9]  = fmaf(v, c4.y, l[9]);
        l[10] = fmaf(v, c4.z, l[10]);  l[11] = fmaf(v, c4.w, l[11]);
        l[12] = fmaf(v, d.x,  l[12]);  l[13] = fmaf(v, d.y,  l[13]);
        l[14] = fmaf(v, d.z,  l[14]);  l[15] = fmaf(v, d.w,  l[15]);
    }
    // reduce across the 8 lanes of each token (lanes are an aligned 8-block)
#pragma unroll
    for (int m = 1; m < 8; m <<= 1)
#pragma unroll
        for (int e = 0; e < NE; ++e)
            l[e] += __shfl_xor_sync(0xffffffffu, l[e], m);

    if (s == 0) {
        float v0 = -1e30f, v1 = -1e30f;
        int i0 = 0, i1 = 0;
#pragma unroll
        for (int e = 0; e < NE; ++e) {
            float lg = l[e] + __ldg(gob + e);
            if (lg > v0)      { v1 = v0; i1 = i0; v0 = lg; i0 = e; }
            else if (lg > v1) { v1 = lg; i1 = e; }
        }
        float e1 = __expf(v1 - v0);
        float sden = 1.f + e1;
        float ga = 1.f / sden;
        float gb2 = e1 / sden;

        const int tok = t0 + t;
        int p0 = atomicAdd(&g_cnt[i0], 1);
        g_rtok[i0 * NTOK + p0]  = tok;
        g_rgate[i0 * NTOK + p0] = ga;
        int p1 = atomicAdd(&g_cnt[i1], 1);
        g_rtok[i1 * NTOK + p1]  = tok;
        g_rgate[i1 * NTOK + p1] = gb2;
    }
}

// ---------------------------------------------------------------------------
// HMMA split-bf16 GEMM. MODE 1: X->H1, 2: H1->H2, 3: H2->out (gated scatter)
// CTA: 128 M-slots x 256 N-cols, K chunked by 64, 2-stage cp.async pipeline.
// 8 warps = 4(M) x 2(N); warp tile 32x128; mma.sync m16n8k16 bf16.
// smem stage: Ahi(16K) | Alo(16K) | Bhi(32K) | Blo(32K) = 96KB; 2 stages.
// B stored [n][k] -> plain ldmatrix (NO trans) yields col-major B frags.
// ---------------------------------------------------------------------------
#define STG_BYTES 98304

template<int MODE, int KF, int NW>
__global__ __launch_bounds__(256, 1) void mma_kernel(
    const float* __restrict__ bias, float* __restrict__ outp)
{
    const int e    = blockIdx.y;
    const int tile = blockIdx.x;
    const int cnt  = g_cnt[e];
    if (tile * 128 >= cnt) return;
    const int nbase = blockIdx.z * 256;
    const int m = min(128, cnt - tile * 128);
    const int slotbase = g_off[e] + tile * 128;

    const __nv_bfloat16* Ahip = (MODE == 1) ? g_xhi : (MODE == 2) ? g_h1hi : g_h2hi;
    const __nv_bfloat16* Alop = (MODE == 1) ? g_xlo : (MODE == 2) ? g_h1lo : g_h2lo;
    const __nv_bfloat16* Bhi_e = ((MODE == 1) ? g_w1Thi : (MODE == 2) ? g_w2Thi : g_w3Thi)
                                 + (size_t)e * NW * KF;
    const __nv_bfloat16* Blo_e = ((MODE == 1) ? g_w1Tlo : (MODE == 2) ? g_w2Tlo : g_w3Tlo)
                                 + (size_t)e * NW * KF;
    __nv_bfloat16* Ohi = (MODE == 1) ? g_h1hi : g_h2hi;
    __nv_bfloat16* Olo = (MODE == 1) ? g_h1lo : g_h2lo;

    extern __shared__ char smp[];
    const uint32_t smb = smem_u32(smp);
    __shared__ int   toks[128];
    __shared__ float gts[128];
    __shared__ float sbias[256];

    const int tid  = threadIdx.x;
    const int wid  = tid >> 5, lane = tid & 31;
    const int wm   = wid & 3,  wn   = wid >> 2;

    if (tid < 128 && MODE != 2) {
        int i = tile * 128 + tid;
        bool v = (i < cnt);
        toks[tid] = v ? g_rtok[e * NTOK + i] : 0;
        gts[tid]  = v ? g_rgate[e * NTOK + i] : 0.f;
    }
    sbias[tid] = bias[e * NW + nbase + tid];
    __syncthreads();

    const int NCH = KF / 64;

    // ---- async chunk loader: 24 cp.async of 16B per thread ----
    auto load_chunk = [&](int ch, int s) {
        const int kbase = ch * 64;
        const uint32_t sb = smb + s * STG_BYTES;
#pragma unroll
        for (int i = 0; i < 4; ++i) {
            int idx = tid + i * 256;          // 0..1023 (A rows)
            int row = idx >> 3, u = idx & 7;
            uint32_t d = sb + row * 128 + ((u ^ (row & 7)) << 4);
            long arow = (MODE == 1) ? (long)toks[row] : (long)(slotbase + row);
            CP16(d,         Ahip + arow * KF + kbase + u * 8);
            CP16(d + 16384, Alop + arow * KF + kbase + u * 8);
        }
#pragma unroll
        for (int i = 0; i < 8; ++i) {
            int idx = tid + i * 256;          // 0..2047 (B rows 0..255)
            int row = idx >> 3, u = idx & 7;
            uint32_t d = sb + 32768 + row * 128 + ((u ^ (row & 7)) << 4);
            CP16(d,         Bhi_e + (size_t)(nbase + row) * KF + kbase + u * 8);
            CP16(d + 32768, Blo_e + (size_t)(nbase + row) * KF + kbase + u * 8);
        }
        CP_COMMIT();
    };

    float acc[2][16][4];
#pragma unroll
    for (int mf = 0; mf < 2; ++mf)
#pragma unroll
        for (int nf = 0; nf < 16; ++nf)
#pragma unroll
            for (int j = 0; j < 4; ++j) acc[mf][nf][j] = 0.f;

    load_chunk(0, 0);

    for (int ch = 0; ch < NCH; ++ch) {
        if (ch + 1 < NCH) { load_chunk(ch + 1, (ch + 1) & 1); CP_WAIT(1); }
        else              { CP_WAIT(0); }
        __syncthreads();

        const uint32_t sb  = smb + (ch & 1) * STG_BYTES;
        const uint32_t aHI = sb, aLO = sb + 16384, bHI = sb + 32768, bLO = sb + 65536;

#pragma unroll
        for (int ks = 0; ks < 4; ++ks) {
            const int k0 = ks * 16;
            // A fragments (row-major 16x16 via ldmatrix.x4)
            uint32_t ahi[2][4], alo[2][4];
            {
                int r_ = (lane & 7) + ((lane >> 3) & 1) * 8;
                int ak = k0 + (lane >> 4) * 8;
#pragma unroll
                for (int mf = 0; mf < 2; ++mf) {
                    int r = wm * 32 + mf * 16 + r_;
                    uint32_t off = (uint32_t)(r * 128 + ((((ak >> 3) ^ (r & 7))) << 4));
                    LDSM4(ahi[mf], aHI + off);
                    LDSM4(alo[mf], aLO + off);
                }
            }
            // B fragments in two groups of 4 x 16-wide tiles (bounds regs)
#pragma unroll
            for (int g = 0; g < 2; ++g) {
                uint32_t bhi[8][2], blo[8][2];
                int n_ = (lane & 7) + (lane >> 4) * 8;
                int bk = k0 + ((lane >> 3) & 1) * 8;
#pragma unroll
                for (int nb = 0; nb < 4; ++nb) {
                    int n = wn * 128 + (g * 4 + nb) * 16 + n_;
                    uint32_t off = (uint32_t)(n * 128 + ((((bk >> 3) ^ (n & 7))) << 4));
                    uint32_t r4[4];
                    LDSM4(r4, bHI + off);
                    bhi[2 * nb][0] = r4[0]; bhi[2 * nb][1] = r4[1];
                    bhi[2 * nb + 1][0] = r4[2]; bhi[2 * nb + 1][1] = r4[3];
                    LDSM4(r4, bLO + off);
                    blo[2 * nb][0] = r4[0]; blo[2 * nb][1] = r4[1];
                    blo[2 * nb + 1][0] = r4[2]; blo[2 * nb + 1][1] = r4[3];
                }
#pragma unroll
                for (int mf = 0; mf < 2; ++mf)
#pragma unroll
                    for (int nf = 0; nf < 8; ++nf)
                        MMA16816(acc[mf][g * 8 + nf], ahi[mf], bhi[nf]);
#pragma unroll
                for (int mf = 0; mf < 2; ++mf)
#pragma unroll
                    for (int nf = 0; nf < 8; ++nf)
                        MMA16816(acc[mf][g * 8 + nf], alo[mf], bhi[nf]);
#pragma unroll
                for (int mf = 0; mf < 2; ++mf)
#pragma unroll
                    for (int nf = 0; nf < 8; ++nf)
                        MMA16816(acc[mf][g * 8 + nf], ahi[mf], blo[nf]);
            }
        }
        __syncthreads();   // all warps done reading before stage is overwritten
    }

    // ---- epilogue ----
    const int grp = lane >> 2, t2 = (lane & 3) * 2;
#pragma unroll
    for (int mf = 0; mf < 2; ++mf) {
#pragma unroll
        for (int nf = 0; nf < 16; ++nf) {
            const float* c = acc[mf][nf];
            const int col = wn * 128 + nf * 8 + t2;       // 0..255 in-tile
#pragma unroll
            for (int half = 0; half < 2; ++half) {
                const int r = wm * 32 + mf * 16 + grp + half * 8;
                float v0 = c[half * 2 + 0] + sbias[col];
                float v1 = c[half * 2 + 1] + sbias[col + 1];
                if (MODE == 3) {
                    if (r < m) {
                        float g = gts[r];
                        float* orow = outp + (size_t)toks[r] * DOUT + nbase + col;
                        atomicAdd(orow,     g * v0);
                        atomicAdd(orow + 1, g * v1);
                    }
                } else {
                    v0 = fmaxf(v0, 0.f);
                    v1 = fmaxf(v1, 0.f);
                    __nv_bfloat16 h0 = __float2bfloat16(v0), h1 = __float2bfloat16(v1);
                    float r0 = v0 - __bfloat162float(h0), r1 = v1 - __bfloat162float(h1);
                    __nv_bfloat16 l0 = __float2bfloat16(r0), l1 = __float2bfloat16(r1);
                    size_t oi = (size_t)(slotbase + r) * NH + nbase + col;
                    *(uint32_t*)(Ohi + oi) =
                        (uint32_t)__bfloat16_as_ushort(h0) | ((uint32_t)__bfloat16_as_ushort(h1) << 16);
                    *(uint32_t*)(Olo + oi) =
                        (uint32_t)__bfloat16_as_ushort(l0) | ((uint32_t)__bfloat16_as_ushort(l1) << 16);
                }
            }
        }
    }
}

// ---------------------------------------------------------------------------
extern "C" void kernel_launch(void* const* d_in, const int* in_sizes, int n_in,
                              void* d_out, int out_size)
{
    const float* x   = (const float*)d_in[0];
    const float* gw  = (const float*)d_in[1];
    const float* gb  = (const float*)d_in[2];
    const float* gow = (const float*)d_in[3];
    const float* gob = (const float*)d_in[4];
    const float* w1  = (const float*)d_in[5];
    const float* b1  = (const float*)d_in[6];
    const float* w2  = (const float*)d_in[7];
    const float* b2  = (const float*)d_in[8];
    const float* w3  = (const float*)d_in[9];
    const float* b3  = (const float*)d_in[10];
    float* out = (float*)d_out;

    // One-time host resources (created on first, uncaptured correctness call)
    static cudaStream_t s_side = nullptr;
    static cudaEvent_t  s_evF = nullptr, s_evJ = nullptr;
    if (!s_side) {
        cudaStreamCreateWithFlags(&s_side, cudaStreamNonBlocking);
        cudaEventCreateWithFlags(&s_evF, cudaEventDisableTiming);
        cudaEventCreateWithFlags(&s_evJ, cudaEventDisableTiming);
    }

    const size_t smg = (size_t)(8192 + 32 * HPAD + NH * GPAD) * sizeof(float);  // ~136 KB
    const int    smm = 2 * STG_BYTES;                                           // 192 KB
    cudaFuncSetAttribute(gate_fused_kernel, cudaFuncAttributeMaxDynamicSharedMemorySize, (int)smg);
    cudaFuncSetAttribute(mma_kernel<1, DIN, NH>,  cudaFuncAttributeMaxDynamicSharedMemorySize, smm);
    cudaFuncSetAttribute(mma_kernel<2, NH, NH>,   cudaFuncAttributeMaxDynamicSharedMemorySize, smm);
    cudaFuncSetAttribute(mma_kernel<3, NH, DOUT>, cudaFuncAttributeMaxDynamicSharedMemorySize, smm);

    // ---- fork: side branch = prep (independent of gate path) ----
    cudaEventRecord(s_evF, 0);
    cudaStreamWaitEvent(s_side, s_evF, 0);

    cudaMemsetAsync(out, 0, (size_t)NTOK * DOUT * sizeof(float), s_side);
    split_x_kernel<<<NTOK * DIN / 2 / 256, 256, 0, s_side>>>(x);
    transpose_split_kernel<1><<<dim3(NH / 32, DIN / 32, NE), dim3(32, 8), 0, s_side>>>(
        w1, NH, (long)NE * NH, DIN, NH);
    transpose_split_kernel<2><<<dim3(NH / 32, NH / 32, NE), dim3(32, 8), 0, s_side>>>(
        w2, NH, (long)NE * NH, NH, NH);
    transpose_split_kernel<3><<<dim3(DOUT / 32, NH / 32, NE), dim3(32, 8), 0, s_side>>>(
        w3, DOUT, (long)NE * DOUT, NH, DOUT);

    // ---- main branch = gate path (hidden GEMM + routing fused) ----
    zero_cnt_kernel<<<1, 32>>>();
    gate_fused_kernel<<<NTOK / 32, 256, smg>>>(x, gw, gb, gow, gob);
    prefix_kernel<<<1, 32>>>();

    // ---- join ----
    cudaEventRecord(s_evJ, s_side);
    cudaStreamWaitEvent(0, s_evJ, 0);

    mma_kernel<1, DIN, NH><<<dim3(64, NE, 2), 256, smm>>>(b1, nullptr);
    mma_kernel<2, NH, NH><<<dim3(64, NE, 2), 256, smm>>>(b2, nullptr);
    mma_kernel<3, NH, DOUT><<<dim3(64, NE, 1), 256, smm>>>(b3, out);
}

// round 9
// speedup vs baseline: 4.6129x; 1.0126x over previous
#include <cuda_runtime.h>
#include <cuda_bf16.h>
#include <cstdint>

#define NTOK 8192
#define DIN  256
#define DOUT 256
#define NE   16
#define NH   512
#define SLOTS 18560   // >= 16384 + 16*127 padded routed slots

// ---------------------------------------------------------------------------
// Device scratch
// ---------------------------------------------------------------------------
__device__ int   g_cnt[NE];
__device__ int   g_off[NE];                // padded prefix offsets
__device__ int   g_rtok[NE * NTOK];
__device__ float g_rgate[NE * NTOK];

__device__ __nv_bfloat16 g_xhi[NTOK * DIN],  g_xlo[NTOK * DIN];
__device__ __nv_bfloat16 g_w1Thi[NE * NH * DIN],  g_w1Tlo[NE * NH * DIN];    // [e][n=512][k=256]
__device__ __nv_bfloat16 g_w2Thi[NE * NH * NH],   g_w2Tlo[NE * NH * NH];     // [e][512][512]
__device__ __nv_bfloat16 g_w3Thi[NE * DOUT * NH], g_w3Tlo[NE * DOUT * NH];   // [e][256][512]
__device__ __nv_bfloat16 g_h1hi[(size_t)SLOTS * NH], g_h1lo[(size_t)SLOTS * NH];
__device__ __nv_bfloat16 g_h2hi[(size_t)SLOTS * NH], g_h2lo[(size_t)SLOTS * NH];

// ---------------------------------------------------------------------------
// PTX helpers (compute_103-safe: cp.async + ldmatrix + mma.sync only)
// ---------------------------------------------------------------------------
__device__ __forceinline__ uint32_t smem_u32(const void* p) {
    uint32_t a;
    asm("{ .reg .u64 t; cvta.to.shared.u64 t, %1; cvt.u32.u64 %0, t; }" : "=r"(a) : "l"(p));
    return a;
}
#define CP16(dst, src) \
    asm volatile("cp.async.cg.shared.global [%0], [%1], 16;" :: "r"(dst), "l"(src) : "memory")
#define CP_COMMIT() asm volatile("cp.async.commit_group;" ::: "memory")
#define CP_WAIT(n)  asm volatile("cp.async.wait_group %0;" :: "n"(n) : "memory")

#define LDSM4(r, addr) \
    asm volatile("ldmatrix.sync.aligned.m8n8.x4.shared.b16 {%0,%1,%2,%3}, [%4];" \
        : "=r"((r)[0]), "=r"((r)[1]), "=r"((r)[2]), "=r"((r)[3]) : "r"(addr))

#define MMA16816(c, a, b) \
    asm volatile("mma.sync.aligned.m16n8k16.row.col.f32.bf16.bf16.f32 " \
        "{%0,%1,%2,%3}, {%4,%5,%6,%7}, {%8,%9}, {%0,%1,%2,%3};" \
        : "+f"((c)[0]), "+f"((c)[1]), "+f"((c)[2]), "+f"((c)[3]) \
        : "r"((a)[0]), "r"((a)[1]), "r"((a)[2]), "r"((a)[3]), "r"((b)[0]), "r"((b)[1]))

// Packed fp32x2 helpers (gate path)
#define FMA2(d, a, b) asm("fma.rn.f32x2 %0, %1, %2, %0;" : "+l"(d) : "l"(a), "l"(b))
#define DUP2(d, s)    asm("mov.b64 %0, {%1, %1};" : "=l"(d) : "f"(s))
#define UNPK(lo, hi, s) asm("mov.b64 {%0, %1}, %2;" : "=f"(lo), "=f"(hi) : "l"(s))

// ---------------------------------------------------------------------------
// Small prep kernels
// ---------------------------------------------------------------------------
__global__ void zero_cnt_kernel() {
    if (threadIdx.x < NE) g_cnt[threadIdx.x] = 0;
}
__global__ void prefix_kernel() {
    if (threadIdx.x == 0) {
        int off = 0;
        for (int e = 0; e < NE; ++e) {
            g_off[e] = off;
            off += ((g_cnt[e] + 127) >> 7) << 7;
        }
    }
}
__global__ void split_x_kernel(const float* __restrict__ x) {
    int i = blockIdx.x * blockDim.x + threadIdx.x;   // pair index
    float2 v = ((const float2*)x)[i];
    __nv_bfloat16 h0 = __float2bfloat16(v.x), h1 = __float2bfloat16(v.y);
    float r0 = v.x - __bfloat162float(h0), r1 = v.y - __bfloat162float(h1);
    __nv_bfloat16 l0 = __float2bfloat16(r0), l1 = __float2bfloat16(r1);
    ((uint32_t*)g_xhi)[i] = (uint32_t)__bfloat16_as_ushort(h0) | ((uint32_t)__bfloat16_as_ushort(h1) << 16);
    ((uint32_t*)g_xlo)[i] = (uint32_t)__bfloat16_as_ushort(l0) | ((uint32_t)__bfloat16_as_ushort(l1) << 16);
}

// Transpose + split: W[k][n] (row stride rs, per-expert col base e_off) -> planes [n][k]
template<int WID>
__global__ void transpose_split_kernel(const float* __restrict__ src,
                                       int e_off, long rs, int K, int N)
{
    __shared__ float t[32][33];
    const int e = blockIdx.z;
    const int n0 = blockIdx.x * 32, k0 = blockIdx.y * 32;
    const int tx = threadIdx.x, ty = threadIdx.y;
    const float* s = src + (long)e * e_off;
#pragma unroll
    for (int i = 0; i < 4; ++i)
        t[ty + 8 * i][tx] = s[(long)(k0 + ty + 8 * i) * rs + n0 + tx];
    __syncthreads();
    __nv_bfloat16* dh = (WID == 1) ? g_w1Thi : (WID == 2) ? g_w2Thi : g_w3Thi;
    __nv_bfloat16* dl = (WID == 1) ? g_w1Tlo : (WID == 2) ? g_w2Tlo : g_w3Tlo;
    dh += (size_t)e * N * K;  dl += (size_t)e * N * K;
#pragma unroll
    for (int i = 0; i < 4; ++i) {
        float v = t[tx][ty + 8 * i];
        __nv_bfloat16 h = __float2bfloat16(v);
        float r = v - __bfloat162float(h);
        size_t idx = (size_t)(n0 + ty + 8 * i) * K + k0 + tx;
        dh[idx] = h;
        dl[idx] = __float2bfloat16(r);
    }
}

// ---------------------------------------------------------------------------
// Fused gate kernel: hidden GEMM (fp32 FFMA2, exact) + logits + top-2 +
// softmax + routing append, all in one kernel. 32 tokens per CTA.
// ---------------------------------------------------------------------------
template<int KDIM>
__device__ __forceinline__ void gemm_coreT(
    const float* __restrict__ St, const float* __restrict__ W, long ws,
    int c0, int c1, unsigned long long* accA, unsigned long long* accB)
{
#pragma unroll 2
    for (int k = 0; k < KDIM; k += 4) {
        const float* wp = W + (long)k * ws;
        unsigned long long ua[4], ub[4];
#pragma unroll
        for (int j = 0; j < 4; ++j) {
            float wa = wp[(long)j * ws + c0];
            float wb = wp[(long)j * ws + c1];
            DUP2(ua[j], wa); DUP2(ub[j], wb);
        }
#pragma unroll
        for (int j = 0; j < 4; ++j) {
            const ulonglong2* xp = (const ulonglong2*)(St + (k + j) * 32);
#pragma unroll
            for (int p = 0; p < 8; ++p) {
                ulonglong2 X = xp[p];
                FMA2(accA[2 * p],     X.x, ua[j]);
                FMA2(accA[2 * p + 1], X.y, ua[j]);
                FMA2(accB[2 * p],     X.x, ub[j]);
                FMA2(accB[2 * p + 1], X.y, ub[j]);
            }
        }
    }
}

#define HPAD 513
#define GPAD 20

__global__ __launch_bounds__(256) void gate_fused_kernel(
    const float* __restrict__ x,  const float* __restrict__ gw,
    const float* __restrict__ gb, const float* __restrict__ gow,
    const float* __restrict__ gob)
{
    extern __shared__ __align__(16) float dynsm[];
    float* Xs  = dynsm;                        // [256][32] transposed x tile
    float* hS  = dynsm + 8192;                 // [32][HPAD]
    float* gwS = dynsm + 8192 + 32 * HPAD;     // [512][GPAD]

    const int tid = threadIdx.x;
    const int wid = tid >> 5, lane = tid & 31;
    const int t0 = blockIdx.x * 32;

    // load x tile transposed [k][r], lane-rotated stores (conflict-free)
    {
        const int fb = wid * 32;
        float v[32];
#pragma unroll
        for (int r = 0; r < 32; ++r)
            v[r] = x[(long)(t0 + r) * DIN + fb + lane];
#pragma unroll
        for (int rr = 0; rr < 32; ++rr) {
            int r = (rr + lane) & 31;
            Xs[(fb + lane) * 32 + r] = v[r];
        }
    }
    __syncthreads();

    const int c0 = tid, c1 = tid + 256;
    unsigned long long accA[16], accB[16];
    float bb0 = gb[c0], bb1 = gb[c1];
#pragma unroll
    for (int p = 0; p < 16; ++p) { DUP2(accA[p], bb0); DUP2(accB[p], bb1); }
    gemm_coreT<DIN>(Xs, gw, NH, c0, c1, accA, accB);

    // write relu'd hidden to smem [token][col]
#pragma unroll
    for (int p = 0; p < 16; ++p) {
        float lo, hi;
        UNPK(lo, hi, accA[p]);
        hS[(2 * p) * HPAD + c0]     = fmaxf(lo, 0.f);
        hS[(2 * p + 1) * HPAD + c0] = fmaxf(hi, 0.f);
        UNPK(lo, hi, accB[p]);
        hS[(2 * p) * HPAD + c1]     = fmaxf(lo, 0.f);
        hS[(2 * p + 1) * HPAD + c1] = fmaxf(hi, 0.f);
    }
    // load gate_out_w into padded smem
    for (int idx = tid; idx < NH * NE; idx += 256) {
        int r = idx >> 4, c = idx & 15;
        gwS[r * GPAD + c] = gow[idx];
    }
    __syncthreads();

    // logits: 8 threads per token, each covers h indices {s, s+8, ..., s+504}
    const int t = tid >> 3, s = tid & 7;
    float l[NE];
#pragma unroll
    for (int e = 0; e < NE; ++e) l[e] = 0.f;
#pragma unroll 4
    for (int i = 0; i < 64; ++i) {
        int hidx = s + 8 * i;
        float v = hS[t * HPAD + hidx];
        const float4* gp = (const float4*)(gwS + hidx * GPAD);
        float4 a = gp[0], b = gp[1], c4 = gp[2], d = gp[3];
        l[0]  = fmaf(v, a.x,  l[0]);   l[1]  = fmaf(v, a.y,  l[1]);
        l[2]  = fmaf(v, a.z,  l[2]);   l[3]  = fmaf(v, a.w,  l[3]);
        l[4]  = fmaf(v, b.x,  l[4]);   l[5]  = fmaf(v, b.y,  l[5]);
        l[6]  = fmaf(v, b.z,  l[6]);   l[7]  = fmaf(v, b.w,  l[7]);
        l[8]  = fmaf(v, c4.x, l[8]);   l[9]  = fmaf(v, c4.y, l[9]);
        l[10] = fmaf(v, c4.z, l[10]);  l[11] = fmaf(v, c4.w, l[11]);
        l[12] = fmaf(v, d.x,  l[12]);  l[13] = fmaf(v, d.y,  l[13]);
        l[14] = fmaf(v, d.z,  l[14]);  l[15] = fmaf(v, d.w,  l[15]);
    }
    // reduce across the 8 lanes of each token (lanes are an aligned 8-block)
#pragma unroll
    for (int m = 1; m < 8; m <<= 1)
#pragma unroll
        for (int e = 0; e < NE; ++e)
            l[e] += __shfl_xor_sync(0xffffffffu, l[e], m);

    if (s == 0) {
        float v0 = -1e30f, v1 = -1e30f;
        int i0 = 0, i1 = 0;
#pragma unroll
        for (int e = 0; e < NE; ++e) {
            float lg = l[e] + __ldg(gob + e);
            if (lg > v0)      { v1 = v0; i1 = i0; v0 = lg; i0 = e; }
            else if (lg > v1) { v1 = lg; i1 = e; }
        }
        float e1 = __expf(v1 - v0);
        float sden = 1.f + e1;
        float ga = 1.f / sden;
        float gb2 = e1 / sden;

        const int tok = t0 + t;
        int p0 = atomicAdd(&g_cnt[i0], 1);
        g_rtok[i0 * NTOK + p0]  = tok;
        g_rgate[i0 * NTOK + p0] = ga;
        int p1 = atomicAdd(&g_cnt[i1], 1);
        g_rtok[i1 * NTOK + p1]  = tok;
        g_rgate[i1 * NTOK + p1] = gb2;
    }
}

// ---------------------------------------------------------------------------
// HMMA split-bf16 GEMM. MODE 1: X->H1, 2: H1->H2, 3: H2->out (gated scatter)
// CTA: 128 M-slots x 256 N-cols, K chunked by 64, 2-stage cp.async pipeline.
// 512 threads, 16 warps = 4(M) x 4(N); warp tile 32x64; mma.sync m16n8k16.
// smem stage: Ahi(16K) | Alo(16K) | Bhi(32K) | Blo(32K) = 96KB; 2 stages.
// B stored [n][k] -> plain ldmatrix (NO trans) yields col-major B frags.
// ---------------------------------------------------------------------------
#define STG_BYTES 98304

template<int MODE, int KF, int NW>
__global__ __launch_bounds__(512, 1) void mma_kernel(
    const float* __restrict__ bias, float* __restrict__ outp)
{
    const int e    = blockIdx.y;
    const int tile = blockIdx.x;
    const int cnt  = g_cnt[e];
    if (tile * 128 >= cnt) return;
    const int nbase = blockIdx.z * 256;
    const int m = min(128, cnt - tile * 128);
    const int slotbase = g_off[e] + tile * 128;

    const __nv_bfloat16* Ahip = (MODE == 1) ? g_xhi : (MODE == 2) ? g_h1hi : g_h2hi;
    const __nv_bfloat16* Alop = (MODE == 1) ? g_xlo : (MODE == 2) ? g_h1lo : g_h2lo;
    const __nv_bfloat16* Bhi_e = ((MODE == 1) ? g_w1Thi : (MODE == 2) ? g_w2Thi : g_w3Thi)
                                 + (size_t)e * NW * KF;
    const __nv_bfloat16* Blo_e = ((MODE == 1) ? g_w1Tlo : (MODE == 2) ? g_w2Tlo : g_w3Tlo)
                                 + (size_t)e * NW * KF;
    __nv_bfloat16* Ohi = (MODE == 1) ? g_h1hi : g_h2hi;
    __nv_bfloat16* Olo = (MODE == 1) ? g_h1lo : g_h2lo;

    extern __shared__ char smp[];
    const uint32_t smb = smem_u32(smp);
    __shared__ int   toks[128];
    __shared__ float gts[128];
    __shared__ float sbias[256];

    const int tid  = threadIdx.x;
    const int wid  = tid >> 5, lane = tid & 31;
    const int wm   = wid & 3,  wn   = wid >> 2;   // 4 x 4 warp grid

    if (tid < 128 && MODE != 2) {
        int i = tile * 128 + tid;
        bool v = (i < cnt);
        toks[tid] = v ? g_rtok[e * NTOK + i] : 0;
        gts[tid]  = v ? g_rgate[e * NTOK + i] : 0.f;
    }
    if (tid < 256) sbias[tid] = bias[e * NW + nbase + tid];
    __syncthreads();

    const int NCH = KF / 64;

    // ---- async chunk loader: 12 cp.async of 16B per thread ----
    auto load_chunk = [&](int ch, int s) {
        const int kbase = ch * 64;
        const uint32_t sb = smb + s * STG_BYTES;
#pragma unroll
        for (int i = 0; i < 2; ++i) {
            int idx = tid + i * 512;          // 0..1023 (A rows)
            int row = idx >> 3, u = idx & 7;
            uint32_t d = sb + row * 128 + ((u ^ (row & 7)) << 4);
            long arow = (MODE == 1) ? (long)toks[row] : (long)(slotbase + row);
            CP16(d,         Ahip + arow * KF + kbase + u * 8);
            CP16(d + 16384, Alop + arow * KF + kbase + u * 8);
        }
#pragma unroll
        for (int i = 0; i < 4; ++i) {
            int idx = tid + i * 512;          // 0..2047 (B rows 0..255)
            int row = idx >> 3, u = idx & 7;
            uint32_t d = sb + 32768 + row * 128 + ((u ^ (row & 7)) << 4);
            CP16(d,         Bhi_e + (size_t)(nbase + row) * KF + kbase + u * 8);
            CP16(d + 32768, Blo_e + (size_t)(nbase + row) * KF + kbase + u * 8);
        }
        CP_COMMIT();
    };

    float acc[2][8][4];
#pragma unroll
    for (int mf = 0; mf < 2; ++mf)
#pragma unroll
        for (int nf = 0; nf < 8; ++nf)
#pragma unroll
            for (int j = 0; j < 4; ++j) acc[mf][nf][j] = 0.f;

    load_chunk(0, 0);

    for (int ch = 0; ch < NCH; ++ch) {
        if (ch + 1 < NCH) { load_chunk(ch + 1, (ch + 1) & 1); CP_WAIT(1); }
        else              { CP_WAIT(0); }
        __syncthreads();

        const uint32_t sb  = smb + (ch & 1) * STG_BYTES;
        const uint32_t aHI = sb, aLO = sb + 16384, bHI = sb + 32768, bLO = sb + 65536;

#pragma unroll
        for (int ks = 0; ks < 4; ++ks) {
            const int k0 = ks * 16;
            // A fragments (row-major 16x16 via ldmatrix.x4)
            uint32_t ahi[2][4], alo[2][4];
            {
                int r_ = (lane & 7) + ((lane >> 3) & 1) * 8;
                int ak = k0 + (lane >> 4) * 8;
#pragma unroll
                for (int mf = 0; mf < 2; ++mf) {
                    int r = wm * 32 + mf * 16 + r_;
                    uint32_t off = (uint32_t)(r * 128 + ((((ak >> 3) ^ (r & 7))) << 4));
                    LDSM4(ahi[mf], aHI + off);
                    LDSM4(alo[mf], aLO + off);
                }
            }
            // B fragments in two groups of 2 x 16-wide tiles (bounds regs)
#pragma unroll
            for (int g = 0; g < 2; ++g) {
                uint32_t bhi[4][2], blo[4][2];
                int n_ = (lane & 7) + (lane >> 4) * 8;
                int bk = k0 + ((lane >> 3) & 1) * 8;
#pragma unroll
                for (int nb = 0; nb < 2; ++nb) {
                    int n = wn * 64 + (g * 2 + nb) * 16 + n_;
                    uint32_t off = (uint32_t)(n * 128 + ((((bk >> 3) ^ (n & 7))) << 4));
                    uint32_t r4[4];
                    LDSM4(r4, bHI + off);
                    bhi[2 * nb][0] = r4[0]; bhi[2 * nb][1] = r4[1];
                    bhi[2 * nb + 1][0] = r4[2]; bhi[2 * nb + 1][1] = r4[3];
                    LDSM4(r4, bLO + off);
                    blo[2 * nb][0] = r4[0]; blo[2 * nb][1] = r4[1];
                    blo[2 * nb + 1][0] = r4[2]; blo[2 * nb + 1][1] = r4[3];
                }
#pragma unroll
                for (int mf = 0; mf < 2; ++mf)
#pragma unroll
                    for (int nf = 0; nf < 4; ++nf)
                        MMA16816(acc[mf][g * 4 + nf], ahi[mf], bhi[nf]);
#pragma unroll
                for (int mf = 0; mf < 2; ++mf)
#pragma unroll
                    for (int nf = 0; nf < 4; ++nf)
                        MMA16816(acc[mf][g * 4 + nf], alo[mf], bhi[nf]);
#pragma unroll
                for (int mf = 0; mf < 2; ++mf)
#pragma unroll
                    for (int nf = 0; nf < 4; ++nf)
                        MMA16816(acc[mf][g * 4 + nf], ahi[mf], blo[nf]);
            }
        }
        __syncthreads();   // all warps done reading before stage is overwritten
    }

    // ---- epilogue ----
    const int grp = lane >> 2, t2 = (lane & 3) * 2;
#pragma unroll
    for (int mf = 0; mf < 2; ++mf) {
#pragma unroll
        for (int nf = 0; nf < 8; ++nf) {
            const float* c = acc[mf][nf];
            const int col = wn * 64 + nf * 8 + t2;        // 0..255 in-tile
#pragma unroll
            for (int half = 0; half < 2; ++half) {
                const int r = wm * 32 + mf * 16 + grp + half * 8;
                float v0 = c[half * 2 + 0] + sbias[col];
                float v1 = c[half * 2 + 1] + sbias[col + 1];
                if (MODE == 3) {
                    if (r < m) {
                        float g = gts[r];
                        float* orow = outp + (size_t)toks[r] * DOUT + nbase + col;
                        atomicAdd(orow,     g * v0);
                        atomicAdd(orow + 1, g * v1);
                    }
                } else {
                    v0 = fmaxf(v0, 0.f);
                    v1 = fmaxf(v1, 0.f);
                    __nv_bfloat16 h0 = __float2bfloat16(v0), h1 = __float2bfloat16(v1);
                    float r0 = v0 - __bfloat162float(h0), r1 = v1 - __bfloat162float(h1);
                    __nv_bfloat16 l0 = __float2bfloat16(r0), l1 = __float2bfloat16(r1);
                    size_t oi = (size_t)(slotbase + r) * NH + nbase + col;
                    *(uint32_t*)(Ohi + oi) =
                        (uint32_t)__bfloat16_as_ushort(h0) | ((uint32_t)__bfloat16_as_ushort(h1) << 16);
                    *(uint32_t*)(Olo + oi) =
                        (uint32_t)__bfloat16_as_ushort(l0) | ((uint32_t)__bfloat16_as_ushort(l1) << 16);
                }
            }
        }
    }
}

// ---------------------------------------------------------------------------
extern "C" void kernel_launch(void* const* d_in, const int* in_sizes, int n_in,
                              void* d_out, int out_size)
{
    const float* x   = (const float*)d_in[0];
    const float* gw  = (const float*)d_in[1];
    const float* gb  = (const float*)d_in[2];
    const float* gow = (const float*)d_in[3];
    const float* gob = (const float*)d_in[4];
    const float* w1  = (const float*)d_in[5];
    const float* b1  = (const float*)d_in[6];
    const float* w2  = (const float*)d_in[7];
    const float* b2  = (const float*)d_in[8];
    const float* w3  = (const float*)d_in[9];
    const float* b3  = (const float*)d_in[10];
    float* out = (float*)d_out;

    // One-time host resources (created on first, uncaptured correctness call)
    static cudaStream_t s_side = nullptr;
    static cudaEvent_t  s_evF = nullptr, s_evJ = nullptr;
    if (!s_side) {
        cudaStreamCreateWithFlags(&s_side, cudaStreamNonBlocking);
        cudaEventCreateWithFlags(&s_evF, cudaEventDisableTiming);
        cudaEventCreateWithFlags(&s_evJ, cudaEventDisableTiming);
    }

    const size_t smg = (size_t)(8192 + 32 * HPAD + NH * GPAD) * sizeof(float);  // ~136 KB
    const int    smm = 2 * STG_BYTES;                                           // 192 KB
    cudaFuncSetAttribute(gate_fused_kernel, cudaFuncAttributeMaxDynamicSharedMemorySize, (int)smg);
    cudaFuncSetAttribute(mma_kernel<1, DIN, NH>,  cudaFuncAttributeMaxDynamicSharedMemorySize, smm);
    cudaFuncSetAttribute(mma_kernel<2, NH, NH>,   cudaFuncAttributeMaxDynamicSharedMemorySize, smm);
    cudaFuncSetAttribute(mma_kernel<3, NH, DOUT>, cudaFuncAttributeMaxDynamicSharedMemorySize, smm);

    // ---- fork: side branch = prep (independent of gate path) ----
    cudaEventRecord(s_evF, 0);
    cudaStreamWaitEvent(s_side, s_evF, 0);

    cudaMemsetAsync(out, 0, (size_t)NTOK * DOUT * sizeof(float), s_side);
    split_x_kernel<<<NTOK * DIN / 2 / 256, 256, 0, s_side>>>(x);
    transpose_split_kernel<1><<<dim3(NH / 32, DIN / 32, NE), dim3(32, 8), 0, s_side>>>(
        w1, NH, (long)NE * NH, DIN, NH);
    transpose_split_kernel<2><<<dim3(NH / 32, NH / 32, NE), dim3(32, 8), 0, s_side>>>(
        w2, NH, (long)NE * NH, NH, NH);
    transpose_split_kernel<3><<<dim3(DOUT / 32, NH / 32, NE), dim3(32, 8), 0, s_side>>>(
        w3, DOUT, (long)NE * DOUT, NH, DOUT);

    // ---- main branch = gate path (hidden GEMM + routing fused) ----
    zero_cnt_kernel<<<1, 32>>>();
    gate_fused_kernel<<<NTOK / 32, 256, smg>>>(x, gw, gb, gow, gob);
    prefix_kernel<<<1, 32>>>();

    // ---- join ----
    cudaEventRecord(s_evJ, s_side);
    cudaStreamWaitEvent(0, s_evJ, 0);

    mma_kernel<1, DIN, NH><<<dim3(64, NE, 2), 512, smm>>>(b1, nullptr);
    mma_kernel<2, NH, NH><<<dim3(64, NE, 2), 512, smm>>>(b2, nullptr);
    mma_kernel<3, NH, DOUT><<<dim3(64, NE, 1), 512, smm>>>(b3, out);
}

// round 10
// speedup vs baseline: 4.6625x; 1.0108x over previous
#include <cuda_runtime.h>
#include <cuda_bf16.h>
#include <cstdint>

#define NTOK 8192
#define DIN  256
#define DOUT 256
#define NE   16
#define NH   512
#define SLOTS 18560   // >= 16384 + 16*127 padded routed slots

// ---------------------------------------------------------------------------
// Device scratch
// ---------------------------------------------------------------------------
__device__ int   g_cnt[NE];
__device__ int   g_rtok[NE * NTOK];
__device__ float g_rgate[NE * NTOK];

__device__ __nv_bfloat16 g_xhi[NTOK * DIN],  g_xlo[NTOK * DIN];
__device__ __nv_bfloat16 g_w1Thi[NE * NH * DIN],  g_w1Tlo[NE * NH * DIN];    // [e][n=512][k=256]
__device__ __nv_bfloat16 g_w2Thi[NE * NH * NH],   g_w2Tlo[NE * NH * NH];     // [e][512][512]
__device__ __nv_bfloat16 g_w3Thi[NE * DOUT * NH], g_w3Tlo[NE * DOUT * NH];   // [e][256][512]
__device__ __nv_bfloat16 g_h1hi[(size_t)SLOTS * NH], g_h1lo[(size_t)SLOTS * NH];
__device__ __nv_bfloat16 g_h2hi[(size_t)SLOTS * NH], g_h2lo[(size_t)SLOTS * NH];

// ---------------------------------------------------------------------------
// PTX helpers (compute_103-safe: cp.async + ldmatrix + mma.sync only)
// ---------------------------------------------------------------------------
__device__ __forceinline__ uint32_t smem_u32(const void* p) {
    uint32_t a;
    asm("{ .reg .u64 t; cvta.to.shared.u64 t, %1; cvt.u32.u64 %0, t; }" : "=r"(a) : "l"(p));
    return a;
}
#define CP16(dst, src) \
    asm volatile("cp.async.cg.shared.global [%0], [%1], 16;" :: "r"(dst), "l"(src) : "memory")
#define CP_COMMIT() asm volatile("cp.async.commit_group;" ::: "memory")
#define CP_WAIT(n)  asm volatile("cp.async.wait_group %0;" :: "n"(n) : "memory")

#define LDSM4(r, addr) \
    asm volatile("ldmatrix.sync.aligned.m8n8.x4.shared.b16 {%0,%1,%2,%3}, [%4];" \
        : "=r"((r)[0]), "=r"((r)[1]), "=r"((r)[2]), "=r"((r)[3]) : "r"(addr))

#define MMA16816(c, a, b) \
    asm volatile("mma.sync.aligned.m16n8k16.row.col.f32.bf16.bf16.f32 " \
        "{%0,%1,%2,%3}, {%4,%5,%6,%7}, {%8,%9}, {%0,%1,%2,%3};" \
        : "+f"((c)[0]), "+f"((c)[1]), "+f"((c)[2]), "+f"((c)[3]) \
        : "r"((a)[0]), "r"((a)[1]), "r"((a)[2]), "r"((a)[3]), "r"((b)[0]), "r"((b)[1]))

// Packed fp32x2 helpers (gate path)
#define FMA2(d, a, b) asm("fma.rn.f32x2 %0, %1, %2, %0;" : "+l"(d) : "l"(a), "l"(b))
#define DUP2(d, s)    asm("mov.b64 %0, {%1, %1};" : "=l"(d) : "f"(s))
#define UNPK(lo, hi, s) asm("mov.b64 {%0, %1}, %2;" : "=f"(lo), "=f"(hi) : "l"(s))

// ---------------------------------------------------------------------------
__global__ void zero_cnt_kernel() {
    if (threadIdx.x < NE) g_cnt[threadIdx.x] = 0;
}

// ---------------------------------------------------------------------------
// Fused prep: split_x + 3 weight transpose+splits, demuxed by blockIdx.x.
//   [0, 4096)        : split x (256 float2 pairs per block)
//   [4096, 6144)     : w1 [DIN,E,NH]  -> planes [e][NH][DIN]   (128 blk/e)
//   [6144, 10240)    : w2 [NH,E,NH]   -> planes [e][NH][NH]    (256 blk/e)
//   [10240, 12288)   : w3 [NH,E,DOUT] -> planes [e][DOUT][NH]  (128 blk/e)
// ---------------------------------------------------------------------------
__global__ __launch_bounds__(256) void prep_kernel(
    const float* __restrict__ x,  const float* __restrict__ w1,
    const float* __restrict__ w2, const float* __restrict__ w3)
{
    const int bid = blockIdx.x;
    const int tid = threadIdx.x;

    if (bid < 4096) {
        int i = bid * 256 + tid;
        float2 v = ((const float2*)x)[i];
        __nv_bfloat16 h0 = __float2bfloat16(v.x), h1 = __float2bfloat16(v.y);
        float r0 = v.x - __bfloat162float(h0), r1 = v.y - __bfloat162float(h1);
        __nv_bfloat16 l0 = __float2bfloat16(r0), l1 = __float2bfloat16(r1);
        ((uint32_t*)g_xhi)[i] = (uint32_t)__bfloat16_as_ushort(h0) | ((uint32_t)__bfloat16_as_ushort(h1) << 16);
        ((uint32_t*)g_xlo)[i] = (uint32_t)__bfloat16_as_ushort(l0) | ((uint32_t)__bfloat16_as_ushort(l1) << 16);
        return;
    }

    __shared__ float t[32][33];
    const int tx = tid & 31, ty = tid >> 5;

    const float* src; long rs; int K, N, e, n0, k0;
    __nv_bfloat16 *dh, *dl;
    if (bid < 6144) {                    // w1
        int l = bid - 4096;
        e = l >> 7; int r = l & 127;
        n0 = (r & 15) * 32; k0 = (r >> 4) * 32;
        src = w1 + e * NH; rs = (long)NE * NH; K = DIN; N = NH;
        dh = g_w1Thi; dl = g_w1Tlo;
    } else if (bid < 10240) {            // w2
        int l = bid - 6144;
        e = l >> 8; int r = l & 255;
        n0 = (r & 15) * 32; k0 = (r >> 4) * 32;
        src = w2 + e * NH; rs = (long)NE * NH; K = NH; N = NH;
        dh = g_w2Thi; dl = g_w2Tlo;
    } else {                             // w3
        int l = bid - 10240;
        e = l >> 7; int r = l & 127;
        n0 = (r & 7) * 32; k0 = (r >> 3) * 32;
        src = w3 + e * DOUT; rs = (long)NE * DOUT; K = NH; N = DOUT;
        dh = g_w3Thi; dl = g_w3Tlo;
    }
    dh += (size_t)e * N * K;
    dl += (size_t)e * N * K;

#pragma unroll
    for (int i = 0; i < 4; ++i)
        t[ty + 8 * i][tx] = src[(long)(k0 + ty + 8 * i) * rs + n0 + tx];
    __syncthreads();
#pragma unroll
    for (int i = 0; i < 4; ++i) {
        float v = t[tx][ty + 8 * i];
        __nv_bfloat16 h = __float2bfloat16(v);
        float r = v - __bfloat162float(h);
        size_t idx = (size_t)(n0 + ty + 8 * i) * K + k0 + tx;
        dh[idx] = h;
        dl[idx] = __float2bfloat16(r);
    }
}

// ---------------------------------------------------------------------------
// Fused gate kernel: hidden GEMM (fp32 FFMA2, exact) + logits + top-2 +
// softmax + routing append, all in one kernel. 32 tokens per CTA.
// ---------------------------------------------------------------------------
template<int KDIM>
__device__ __forceinline__ void gemm_coreT(
    const float* __restrict__ St, const float* __restrict__ W, long ws,
    int c0, int c1, unsigned long long* accA, unsigned long long* accB)
{
#pragma unroll 2
    for (int k = 0; k < KDIM; k += 4) {
        const float* wp = W + (long)k * ws;
        unsigned long long ua[4], ub[4];
#pragma unroll
        for (int j = 0; j < 4; ++j) {
            float wa = wp[(long)j * ws + c0];
            float wb = wp[(long)j * ws + c1];
            DUP2(ua[j], wa); DUP2(ub[j], wb);
        }
#pragma unroll
        for (int j = 0; j < 4; ++j) {
            const ulonglong2* xp = (const ulonglong2*)(St + (k + j) * 32);
#pragma unroll
            for (int p = 0; p < 8; ++p) {
                ulonglong2 X = xp[p];
                FMA2(accA[2 * p],     X.x, ua[j]);
                FMA2(accA[2 * p + 1], X.y, ua[j]);
                FMA2(accB[2 * p],     X.x, ub[j]);
                FMA2(accB[2 * p + 1], X.y, ub[j]);
            }
        }
    }
}

#define HPAD 513
#define GPAD 20

__global__ __launch_bounds__(256) void gate_fused_kernel(
    const float* __restrict__ x,  const float* __restrict__ gw,
    const float* __restrict__ gb, const float* __restrict__ gow,
    const float* __restrict__ gob)
{
    extern __shared__ __align__(16) float dynsm[];
    float* Xs  = dynsm;                        // [256][32] transposed x tile
    float* hS  = dynsm + 8192;                 // [32][HPAD]
    float* gwS = dynsm + 8192 + 32 * HPAD;     // [512][GPAD]

    const int tid = threadIdx.x;
    const int wid = tid >> 5, lane = tid & 31;
    const int t0 = blockIdx.x * 32;

    // load x tile transposed [k][r], lane-rotated stores (conflict-free)
    {
        const int fb = wid * 32;
        float v[32];
#pragma unroll
        for (int r = 0; r < 32; ++r)
            v[r] = x[(long)(t0 + r) * DIN + fb + lane];
#pragma unroll
        for (int rr = 0; rr < 32; ++rr) {
            int r = (rr + lane) & 31;
            Xs[(fb + lane) * 32 + r] = v[r];
        }
    }
    __syncthreads();

    const int c0 = tid, c1 = tid + 256;
    unsigned long long accA[16], accB[16];
    float bb0 = gb[c0], bb1 = gb[c1];
#pragma unroll
    for (int p = 0; p < 16; ++p) { DUP2(accA[p], bb0); DUP2(accB[p], bb1); }
    gemm_coreT<DIN>(Xs, gw, NH, c0, c1, accA, accB);

    // write relu'd hidden to smem [token][col]
#pragma unroll
    for (int p = 0; p < 16; ++p) {
        float lo, hi;
        UNPK(lo, hi, accA[p]);
        hS[(2 * p) * HPAD + c0]     = fmaxf(lo, 0.f);
        hS[(2 * p + 1) * HPAD + c0] = fmaxf(hi, 0.f);
        UNPK(lo, hi, accB[p]);
        hS[(2 * p) * HPAD + c1]     = fmaxf(lo, 0.f);
        hS[(2 * p + 1) * HPAD + c1] = fmaxf(hi, 0.f);
    }
    // load gate_out_w into padded smem
    for (int idx = tid; idx < NH * NE; idx += 256) {
        int r = idx >> 4, c = idx & 15;
        gwS[r * GPAD + c] = gow[idx];
    }
    __syncthreads();

    // logits: 8 threads per token, each covers h indices {s, s+8, ..., s+504}
    const int t = tid >> 3, s = tid & 7;
    float l[NE];
#pragma unroll
    for (int e = 0; e < NE; ++e) l[e] = 0.f;
#pragma unroll 4
    for (int i = 0; i < 64; ++i) {
        int hidx = s + 8 * i;
        float v = hS[t * HPAD + hidx];
        const float4* gp = (const float4*)(gwS + hidx * GPAD);
        float4 a = gp[0], b = gp[1], c4 = gp[2], d = gp[3];
        l[0]  = fmaf(v, a.x,  l[0]);   l[1]  = fmaf(v, a.y,  l[1]);
        l[2]  = fmaf(v, a.z,  l[2]);   l[3]  = fmaf(v, a.w,  l[3]);
        l[4]  = fmaf(v, b.x,  l[4]);   l[5]  = fmaf(v, b.y,  l[5]);
        l[6]  = fmaf(v, b.z,  l[6]);   l[7]  = fmaf(v, b.w,  l[7]);
        l[8]  = fmaf(v, c4.x, l[8]);   l[9]  = fmaf(v, c4.y, l[9]);
        l[10] = fmaf(v, c4.z, l[10]);  l[11] = fmaf(v, c4.w, l[11]);
        l[12] = fmaf(v, d.x,  l[12]);  l[13] = fmaf(v, d.y,  l[13]);
        l[14] = fmaf(v, d.z,  l[14]);  l[15] = fmaf(v, d.w,  l[15]);
    }
    // reduce across the 8 lanes of each token (lanes are an aligned 8-block)
#pragma unroll
    for (int m = 1; m < 8; m <<= 1)
#pragma unroll
        for (int e = 0; e < NE; ++e)
            l[e] += __shfl_xor_sync(0xffffffffu, l[e], m);

    if (s == 0) {
        float v0 = -1e30f, v1 = -1e30f;
        int i0 = 0, i1 = 0;
#pragma unroll
        for (int e = 0; e < NE; ++e) {
            float lg = l[e] + __ldg(gob + e);
            if (lg > v0)      { v1 = v0; i1 = i0; v0 = lg; i0 = e; }
            else if (lg > v1) { v1 = lg; i1 = e; }
        }
        float e1 = __expf(v1 - v0);
        float sden = 1.f + e1;
        float ga = 1.f / sden;
        float gb2 = e1 / sden;

        const int tok = t0 + t;
        int p0 = atomicAdd(&g_cnt[i0], 1);
        g_rtok[i0 * NTOK + p0]  = tok;
        g_rgate[i0 * NTOK + p0] = ga;
        int p1 = atomicAdd(&g_cnt[i1], 1);
        g_rtok[i1 * NTOK + p1]  = tok;
        g_rgate[i1 * NTOK + p1] = gb2;
    }
}

// ---------------------------------------------------------------------------
// HMMA split-bf16 GEMM. MODE 1: X->H1, 2: H1->H2, 3: H2->out (gated scatter)
// CTA: 128 M-slots x 256 N-cols, K chunked by 64, 2-stage cp.async pipeline.
// 512 threads, 16 warps = 4(M) x 4(N); warp tile 32x64; mma.sync m16n8k16.
// Slot offsets computed inline from g_cnt (no prefix kernel).
// ---------------------------------------------------------------------------
#define STG_BYTES 98304

template<int MODE, int KF, int NW>
__global__ __launch_bounds__(512, 1) void mma_kernel(
    const float* __restrict__ bias, float* __restrict__ outp)
{
    const int e    = blockIdx.y;
    const int tile = blockIdx.x;
    const int cnt  = g_cnt[e];
    if (tile * 128 >= cnt) return;
    const int nbase = blockIdx.z * 256;
    const int m = min(128, cnt - tile * 128);

    int off = 0;
#pragma unroll
    for (int i = 0; i < NE; ++i)
        if (i < e) off += ((g_cnt[i] + 127) >> 7) << 7;
    const int slotbase = off + tile * 128;

    const __nv_bfloat16* Ahip = (MODE == 1) ? g_xhi : (MODE == 2) ? g_h1hi : g_h2hi;
    const __nv_bfloat16* Alop = (MODE == 1) ? g_xlo : (MODE == 2) ? g_h1lo : g_h2lo;
    const __nv_bfloat16* Bhi_e = ((MODE == 1) ? g_w1Thi : (MODE == 2) ? g_w2Thi : g_w3Thi)
                                 + (size_t)e * NW * KF;
    const __nv_bfloat16* Blo_e = ((MODE == 1) ? g_w1Tlo : (MODE == 2) ? g_w2Tlo : g_w3Tlo)
                                 + (size_t)e * NW * KF;
    __nv_bfloat16* Ohi = (MODE == 1) ? g_h1hi : g_h2hi;
    __nv_bfloat16* Olo = (MODE == 1) ? g_h1lo : g_h2lo;

    extern __shared__ char smp[];
    const uint32_t smb = smem_u32(smp);
    __shared__ int   toks[128];
    __shared__ float gts[128];
    __shared__ float sbias[256];

    const int tid  = threadIdx.x;
    const int wid  = tid >> 5, lane = tid & 31;
    const int wm   = wid & 3,  wn   = wid >> 2;   // 4 x 4 warp grid

    if (tid < 128 && MODE != 2) {
        int i = tile * 128 + tid;
        bool v = (i < cnt);
        toks[tid] = v ? g_rtok[e * NTOK + i] : 0;
        gts[tid]  = v ? g_rgate[e * NTOK + i] : 0.f;
    }
    if (tid < 256) sbias[tid] = bias[e * NW + nbase + tid];
    __syncthreads();

    const int NCH = KF / 64;

    // ---- async chunk loader: 12 cp.async of 16B per thread ----
    auto load_chunk = [&](int ch, int s) {
        const int kbase = ch * 64;
        const uint32_t sb = smb + s * STG_BYTES;
#pragma unroll
        for (int i = 0; i < 2; ++i) {
            int idx = tid + i * 512;          // 0..1023 (A rows)
            int row = idx >> 3, u = idx & 7;
            uint32_t d = sb + row * 128 + ((u ^ (row & 7)) << 4);
            long arow = (MODE == 1) ? (long)toks[row] : (long)(slotbase + row);
            CP16(d,         Ahip + arow * KF + kbase + u * 8);
            CP16(d + 16384, Alop + arow * KF + kbase + u * 8);
        }
#pragma unroll
        for (int i = 0; i < 4; ++i) {
            int idx = tid + i * 512;          // 0..2047 (B rows 0..255)
            int row = idx >> 3, u = idx & 7;
            uint32_t d = sb + 32768 + row * 128 + ((u ^ (row & 7)) << 4);
            CP16(d,         Bhi_e + (size_t)(nbase + row) * KF + kbase + u * 8);
            CP16(d + 32768, Blo_e + (size_t)(nbase + row) * KF + kbase + u * 8);
        }
        CP_COMMIT();
    };

    float acc[2][8][4];
#pragma unroll
    for (int mf = 0; mf < 2; ++mf)
#pragma unroll
        for (int nf = 0; nf < 8; ++nf)
#pragma unroll
            for (int j = 0; j < 4; ++j) acc[mf][nf][j] = 0.f;

    load_chunk(0, 0);

    for (int ch = 0; ch < NCH; ++ch) {
        if (ch + 1 < NCH) { load_chunk(ch + 1, (ch + 1) & 1); CP_WAIT(1); }
        else              { CP_WAIT(0); }
        __syncthreads();

        const uint32_t sb  = smb + (ch & 1) * STG_BYTES;
        const uint32_t aHI = sb, aLO = sb + 16384, bHI = sb + 32768, bLO = sb + 65536;

#pragma unroll
        for (int ks = 0; ks < 4; ++ks) {
            const int k0 = ks * 16;
            // A fragments (row-major 16x16 via ldmatrix.x4)
            uint32_t ahi[2][4], alo[2][4];
            {
                int r_ = (lane & 7) + ((lane >> 3) & 1) * 8;
                int ak = k0 + (lane >> 4) * 8;
#pragma unroll
                for (int mf = 0; mf < 2; ++mf) {
                    int r = wm * 32 + mf * 16 + r_;
                    uint32_t off2 = (uint32_t)(r * 128 + ((((ak >> 3) ^ (r & 7))) << 4));
                    LDSM4(ahi[mf], aHI + off2);
                    LDSM4(alo[mf], aLO + off2);
                }
            }
            // B fragments in two groups of 2 x 16-wide tiles (bounds regs)
#pragma unroll
            for (int g = 0; g < 2; ++g) {
                uint32_t bhi[4][2], blo[4][2];
                int n_ = (lane & 7) + (lane >> 4) * 8;
                int bk = k0 + ((lane >> 3) & 1) * 8;
#pragma unroll
                for (int nb = 0; nb < 2; ++nb) {
                    int n = wn * 64 + (g * 2 + nb) * 16 + n_;
                    uint32_t off2 = (uint32_t)(n * 128 + ((((bk >> 3) ^ (n & 7))) << 4));
                    uint32_t r4[4];
                    LDSM4(r4, bHI + off2);
                    bhi[2 * nb][0] = r4[0]; bhi[2 * nb][1] = r4[1];
                    bhi[2 * nb + 1][0] = r4[2]; bhi[2 * nb + 1][1] = r4[3];
                    LDSM4(r4, bLO + off2);
                    blo[2 * nb][0] = r4[0]; blo[2 * nb][1] = r4[1];
                    blo[2 * nb + 1][0] = r4[2]; blo[2 * nb + 1][1] = r4[3];
                }
#pragma unroll
                for (int mf = 0; mf < 2; ++mf)
#pragma unroll
                    for (int nf = 0; nf < 4; ++nf)
                        MMA16816(acc[mf][g * 4 + nf], ahi[mf], bhi[nf]);
#pragma unroll
                for (int mf = 0; mf < 2; ++mf)
#pragma unroll
                    for (int nf = 0; nf < 4; ++nf)
                        MMA16816(acc[mf][g * 4 + nf], alo[mf], bhi[nf]);
#pragma unroll
                for (int mf = 0; mf < 2; ++mf)
#pragma unroll
                    for (int nf = 0; nf < 4; ++nf)
                        MMA16816(acc[mf][g * 4 + nf], ahi[mf], blo[nf]);
            }
        }
        __syncthreads();   // all warps done reading before stage is overwritten
    }

    // ---- epilogue ----
    const int grp = lane >> 2, t2 = (lane & 3) * 2;
#pragma unroll
    for (int mf = 0; mf < 2; ++mf) {
#pragma unroll
        for (int nf = 0; nf < 8; ++nf) {
            const float* c = acc[mf][nf];
            const int col = wn * 64 + nf * 8 + t2;        // 0..255 in-tile
#pragma unroll
            for (int half = 0; half < 2; ++half) {
                const int r = wm * 32 + mf * 16 + grp + half * 8;
                float v0 = c[half * 2 + 0] + sbias[col];
                float v1 = c[half * 2 + 1] + sbias[col + 1];
                if (MODE == 3) {
                    if (r < m) {
                        float g = gts[r];
                        float* orow = outp + (size_t)toks[r] * DOUT + nbase + col;
                        atomicAdd(orow,     g * v0);
                        atomicAdd(orow + 1, g * v1);
                    }
                } else {
                    v0 = fmaxf(v0, 0.f);
                    v1 = fmaxf(v1, 0.f);
                    __nv_bfloat16 h0 = __float2bfloat16(v0), h1 = __float2bfloat16(v1);
                    float r0 = v0 - __bfloat162float(h0), r1 = v1 - __bfloat162float(h1);
                    __nv_bfloat16 l0 = __float2bfloat16(r0), l1 = __float2bfloat16(r1);
                    size_t oi = (size_t)(slotbase + r) * NH + nbase + col;
                    *(uint32_t*)(Ohi + oi) =
                        (uint32_t)__bfloat16_as_ushort(h0) | ((uint32_t)__bfloat16_as_ushort(h1) << 16);
                    *(uint32_t*)(Olo + oi) =
                        (uint32_t)__bfloat16_as_ushort(l0) | ((uint32_t)__bfloat16_as_ushort(l1) << 16);
                }
            }
        }
    }
}

// ---------------------------------------------------------------------------
extern "C" void kernel_launch(void* const* d_in, const int* in_sizes, int n_in,
                              void* d_out, int out_size)
{
    const float* x   = (const float*)d_in[0];
    const float* gw  = (const float*)d_in[1];
    const float* gb  = (const float*)d_in[2];
    const float* gow = (const float*)d_in[3];
    const float* gob = (const float*)d_in[4];
    const float* w1  = (const float*)d_in[5];
    const float* b1  = (const float*)d_in[6];
    const float* w2  = (const float*)d_in[7];
    const float* b2  = (const float*)d_in[8];
    const float* w3  = (const float*)d_in[9];
    const float* b3  = (const float*)d_in[10];
    float* out = (float*)d_out;

    // One-time host resources (created on first, uncaptured correctness call)
    static cudaStream_t s_side = nullptr;
    static cudaEvent_t  s_evF = nullptr, s_evJ = nullptr;
    if (!s_side) {
        cudaStreamCreateWithFlags(&s_side, cudaStreamNonBlocking);
        cudaEventCreateWithFlags(&s_evF, cudaEventDisableTiming);
        cudaEventCreateWithFlags(&s_evJ, cudaEventDisableTiming);
    }

    const size_t smg = (size_t)(8192 + 32 * HPAD + NH * GPAD) * sizeof(float);  // ~136 KB
    const int    smm = 2 * STG_BYTES;                                           // 192 KB
    cudaFuncSetAttribute(gate_fused_kernel, cudaFuncAttributeMaxDynamicSharedMemorySize, (int)smg);
    cudaFuncSetAttribute(mma_kernel<1, DIN, NH>,  cudaFuncAttributeMaxDynamicSharedMemorySize, smm);
    cudaFuncSetAttribute(mma_kernel<2, NH, NH>,   cudaFuncAttributeMaxDynamicSharedMemorySize, smm);
    cudaFuncSetAttribute(mma_kernel<3, NH, DOUT>, cudaFuncAttributeMaxDynamicSharedMemorySize, smm);

    // ---- fork ----
    cudaEventRecord(s_evF, 0);
    cudaStreamWaitEvent(s_side, s_evF, 0);

    // main branch = gate path (launches #1, #2)
    zero_cnt_kernel<<<1, 32>>>();
    gate_fused_kernel<<<NTOK / 32, 256, smg>>>(x, gw, gb, gow, gob);

    // side branch = prep (launch #3) + memset
    cudaMemsetAsync(out, 0, (size_t)NTOK * DOUT * sizeof(float), s_side);
    prep_kernel<<<12288, 256, 0, s_side>>>(x, w1, w2, w3);

    // ---- join ----
    cudaEventRecord(s_evJ, s_side);
    cudaStreamWaitEvent(0, s_evJ, 0);

    // mma_kernel<1> is kernel launch #4 -> ncu (-s 5 -c 1) profiles it
    mma_kernel<1, DIN, NH><<<dim3(64, NE, 2), 512, smm>>>(b1, nullptr);
    mma_kernel<2, NH, NH><<<dim3(64, NE, 2), 512, smm>>>(b2, nullptr);
    mma_kernel<3, NH, DOUT><<<dim3(64, NE, 1), 512, smm>>>(b3, out);
}